// round 9
// baseline (speedup 1.0000x reference)
#include <cuda_runtime.h>
#include <cuda_fp16.h>
#include <cstdint>
#include <cstddef>
#include <math.h>

#define G_    8192
#define IND_  512
#define KQD_  128
#define OUTD_ 512
#define NP_   768     // packed k|q|v columns

// ---------------- scratch (static __device__ = allowed) --------------------
__device__ __half h_x[(size_t)G_ * IND_];
__device__ __half h_w[(size_t)NP_ * IND_];     // packed [Wk;Wq;Wv]
__device__ float  g_bias[NP_];                 // packed [bk;bq;bv]
__device__ __half h_kqv[(size_t)G_ * NP_];     // packed [k|q|v]
__device__ __half h_vt[(size_t)OUTD_ * G_];
__device__ __half h_s[(size_t)G_ * G_];
__device__ float  g_sumsq[G_];
__device__ float  g_rinv[G_];

// ---------------- helpers ---------------------------------------------------
__device__ __forceinline__ uint32_t smem_u32(const void* p) {
    uint32_t a;
    asm("{ .reg .u64 t; cvta.to.shared.u64 t, %1; cvt.u32.u64 %0, t; }"
        : "=r"(a) : "l"(p));
    return a;
}
#define CP_ASYNC16(sm, gm) \
    asm volatile("cp.async.cg.shared.global [%0], [%1], 16;" :: "r"(sm), "l"(gm))
#define CP_COMMIT() asm volatile("cp.async.commit_group;" ::: "memory")
#define CP_WAIT(n)  asm volatile("cp.async.wait_group %0;" :: "n"(n) : "memory")

#define LDMX4(r0, r1, r2, r3, addr) \
    asm volatile("ldmatrix.sync.aligned.m8n8.x4.shared.b16 {%0,%1,%2,%3}, [%4];" \
                 : "=r"(r0), "=r"(r1), "=r"(r2), "=r"(r3) : "r"(addr))

__device__ __forceinline__ void mma_f16(float* c, const uint32_t* a, const uint32_t* b) {
    asm volatile(
        "mma.sync.aligned.m16n8k16.row.col.f32.f16.f16.f32 "
        "{%0,%1,%2,%3}, {%4,%5,%6,%7}, {%8,%9}, {%0,%1,%2,%3};"
        : "+f"(c[0]), "+f"(c[1]), "+f"(c[2]), "+f"(c[3])
        : "r"(a[0]), "r"(a[1]), "r"(a[2]), "r"(a[3]), "r"(b[0]), "r"(b[1]));
}

// ===========================================================================
// FP16 GEMM-NT:  C[M,N] = A[M,K] @ B[N,K]^T   (half, row-major, strided lds)
// Block 128x128, BK=32 halves, 4 warps (128 thr), warp tile 64x64,
// 5-stage cp.async (2 CTA/SM), whole-stage fragment hoist -> 64-MMA bursts.
// MODE 0: Ch = h(acc + bias[col])                 (proj; aux_f = bias fp32)
// MODE 1: Ch = h(acc), sumsq[row] += row sumsq    (scores)
// MODE 2: Cf = rinv[row]*acc + float(aux_h[row*ldaux+col]) (final)
// ===========================================================================
template<int MODE>
__global__ void __launch_bounds__(128, 2)
mma_gemm(const __half* __restrict__ A, const __half* __restrict__ B,
         const float* __restrict__ aux_f, const __half* __restrict__ aux_h,
         const float* __restrict__ rinv,
         __half* __restrict__ Ch, float* __restrict__ Cf,
         float* __restrict__ sumsq,
         int K, int lda, int ldb, int ldc, int ldaux)
{
    constexpr int STAGES = 5;
    constexpr int AS = 128 * 40;   // halves per A stage (row stride 40 halves = 80B)
    constexpr int BS = 128 * 40;

    extern __shared__ __half sm[];
    const uint32_t sAu = smem_u32(sm);
    const uint32_t sBu = smem_u32(sm + STAGES * AS);

    const int tid  = threadIdx.x;
    const int warp = tid >> 5;
    const int lane = tid & 31;
    const int gr   = lane >> 2;
    const int tc   = lane & 3;
    const int wm   = (warp & 1) * 64;
    const int wn   = (warp >> 1) * 64;
    const int rowBase = blockIdx.y * 128;
    const int colBase = blockIdx.x * 128;

    // ldmatrix selects (half units)
    const int aRow  = wm + (lane & 15);
    const int aColH = (lane >> 4) << 3;                       // 0 or 8 halves
    const int bRow  = wn + ((lane >> 4) << 3) + (lane & 7);
    const int bColH = ((lane >> 3) & 1) << 3;                 // 0 or 8 halves

    float acc[4][8][4];
#pragma unroll
    for (int mi = 0; mi < 4; mi++)
#pragma unroll
        for (int ni = 0; ni < 8; ni++)
#pragma unroll
            for (int r = 0; r < 4; r++) acc[mi][ni][r] = 0.f;

    const int T = K / 32;   // 32 halves per stage

    auto load_stage = [&](int it, int buf) {
        const int k0 = it * 32;
#pragma unroll
        for (int l = 0; l < 4; l++) {
            int c = tid + l * 128;
            int r = c >> 2, ck = (c & 3) * 8;                 // 8 halves = 16B
            CP_ASYNC16(sAu + (uint32_t)(buf * AS + r * 40 + ck) * 2,
                       A + (size_t)(rowBase + r) * lda + k0 + ck);
        }
#pragma unroll
        for (int l = 0; l < 4; l++) {
            int c = tid + l * 128;
            int r = c >> 2, ck = (c & 3) * 8;
            CP_ASYNC16(sBu + (uint32_t)(buf * BS + r * 40 + ck) * 2,
                       B + (size_t)(colBase + r) * ldb + k0 + ck);
        }
        CP_COMMIT();
    };

#pragma unroll
    for (int s = 0; s < STAGES - 1; s++)
        if (s < T) load_stage(s, s);

    int buf = 0;
    for (int i = 0; i < T; i++) {
        const int rem = T - 1 - i;
        if (rem >= 3)      { CP_WAIT(3); }
        else if (rem == 2) { CP_WAIT(2); }
        else if (rem == 1) { CP_WAIT(1); }
        else               { CP_WAIT(0); }
        __syncthreads();
        if (i + STAGES - 1 < T) {
            int nb = buf + STAGES - 1; if (nb >= STAGES) nb -= STAGES;
            load_stage(i + STAGES - 1, nb);
        }

        const uint32_t cA = sAu + (uint32_t)(buf * AS) * 2;
        const uint32_t cB = sBu + (uint32_t)(buf * BS) * 2;

        // ---- hoist ALL fragments for this BK=32 stage (both k16 halves) ----
        uint32_t a[2][4][4], b[2][8][2];
#pragma unroll
        for (int ks = 0; ks < 2; ks++) {
            const int kk = ks * 16;
#pragma unroll
            for (int mi = 0; mi < 4; mi++) {
                uint32_t ad = cA + (uint32_t)((aRow + mi * 16) * 40 + kk + aColH) * 2;
                LDMX4(a[ks][mi][0], a[ks][mi][1], a[ks][mi][2], a[ks][mi][3], ad);
            }
#pragma unroll
            for (int p = 0; p < 4; p++) {
                uint32_t bd = cB + (uint32_t)((bRow + p * 16) * 40 + kk + bColH) * 2;
                LDMX4(b[ks][2 * p][0], b[ks][2 * p][1],
                      b[ks][2 * p + 1][0], b[ks][2 * p + 1][1], bd);
            }
        }
        // ---- 64-MMA burst ----
#pragma unroll
        for (int ks = 0; ks < 2; ks++)
#pragma unroll
            for (int mi = 0; mi < 4; mi++)
#pragma unroll
                for (int ni = 0; ni < 8; ni++)
                    mma_f16(acc[mi][ni], a[ks][mi], b[ks][ni]);

        buf++; if (buf >= STAGES) buf -= STAGES;
    }

    // ---------------- epilogue ----------------
#pragma unroll
    for (int mi = 0; mi < 4; mi++) {
#pragma unroll
        for (int h = 0; h < 2; h++) {
            const int row = rowBase + wm + mi * 16 + h * 8 + gr;
            float rv = 0.f;
            if (MODE == 2) rv = rinv[row];
            float ss = 0.f;
#pragma unroll
            for (int ni = 0; ni < 8; ni++) {
                const int col = colBase + wn + ni * 8 + tc * 2;
                float v0 = acc[mi][ni][h * 2 + 0];
                float v1 = acc[mi][ni][h * 2 + 1];
                if (MODE == 0) {
                    __half2 o = __floats2half2_rn(v0 + aux_f[col], v1 + aux_f[col + 1]);
                    *reinterpret_cast<__half2*>(Ch + (size_t)row * ldc + col) = o;
                } else if (MODE == 1) {
                    __half2 o = __floats2half2_rn(v0, v1);
                    float2 of = __half22float2(o);
                    ss += of.x * of.x + of.y * of.y;
                    *reinterpret_cast<__half2*>(Ch + (size_t)row * ldc + col) = o;
                } else {
                    float2 res = __half22float2(
                        *reinterpret_cast<const __half2*>(aux_h + (size_t)row * ldaux + col));
                    float2 o;
                    o.x = rv * v0 + res.x;
                    o.y = rv * v1 + res.y;
                    *reinterpret_cast<float2*>(Cf + (size_t)row * ldc + col) = o;
                }
            }
            if (MODE == 1) {
                ss += __shfl_xor_sync(0xffffffffu, ss, 1);
                ss += __shfl_xor_sync(0xffffffffu, ss, 2);
                if (tc == 0) atomicAdd(&sumsq[row], ss);
            }
        }
    }
}

// ---------------------------------------------------------------------------
__global__ void f2h(const float* __restrict__ in, __half* __restrict__ out, int n2)
{
    int i = blockIdx.x * 256 + threadIdx.x;
    if (i < n2) {
        float2 v = reinterpret_cast<const float2*>(in)[i];
        reinterpret_cast<__half2*>(out)[i] = __floats2half2_rn(v.x, v.y);
    }
}

// pack [Wk;Wq;Wv] -> h_w [768x512] fp16
__global__ void pack_w(const float* __restrict__ wk, const float* __restrict__ wq,
                       const float* __restrict__ wv, __half* __restrict__ out)
{
    int i = blockIdx.x * 256 + threadIdx.x;        // over 768*512/2
    if (i >= NP_ * IND_ / 2) return;
    int row = i / (IND_ / 2);
    int c2  = i % (IND_ / 2);
    const float* src; int sr;
    if (row < KQD_)          { src = wk; sr = row; }
    else if (row < 2 * KQD_) { src = wq; sr = row - KQD_; }
    else                     { src = wv; sr = row - 2 * KQD_; }
    float2 v = reinterpret_cast<const float2*>(src + (size_t)sr * IND_)[c2];
    reinterpret_cast<__half2*>(out + (size_t)row * IND_)[c2] = __floats2half2_rn(v.x, v.y);
}

__global__ void pack_bias(const float* __restrict__ bk, const float* __restrict__ bq,
                          const float* __restrict__ bv, float* __restrict__ out)
{
    int i = threadIdx.x;   // 768 threads
    if (i < KQD_)          out[i] = bk[i];
    else if (i < 2 * KQD_) out[i] = bq[i - KQD_];
    else                   out[i] = bv[i - 2 * KQD_];
}

// transpose V (strided source inside packed kqv) -> h_vt [512 x 8192]
__global__ void transpose_h(const __half* __restrict__ in, int ldin,
                            __half* __restrict__ out)
{
    __shared__ __half t[32][33];
    int x  = blockIdx.x * 32 + threadIdx.x;   // col of V (0..511)
    int y0 = blockIdx.y * 32;                 // row of V
#pragma unroll
    for (int i = threadIdx.y; i < 32; i += 8)
        t[i][threadIdx.x] = in[(size_t)(y0 + i) * ldin + x];
    __syncthreads();
    int ox  = y0 + threadIdx.x;
    int oy0 = blockIdx.x * 32;
#pragma unroll
    for (int i = threadIdx.y; i < 32; i += 8)
        out[(size_t)(oy0 + i) * G_ + ox] = t[threadIdx.x][i];
}

__global__ void rinv_kernel(const float* __restrict__ ss, float* __restrict__ rinv)
{
    int i = blockIdx.x * 256 + threadIdx.x;
    float n = sqrtf(ss[i]);
    rinv[i] = 1.0f / fmaxf(n, 1e-12f);
}

// ---------------------------------------------------------------------------
extern "C" void kernel_launch(void* const* d_in, const int* in_sizes, int n_in,
                              void* d_out, int out_size)
{
    const float* x  = (const float*)d_in[0];
    const float* Wk = (const float*)d_in[1];
    const float* bk = (const float*)d_in[2];
    const float* Wq = (const float*)d_in[3];
    const float* bq = (const float*)d_in[4];
    const float* Wv = (const float*)d_in[5];
    const float* bv = (const float*)d_in[6];
    float* out = (float*)d_out;
    (void)in_sizes; (void)n_in; (void)out_size;

    __half *px, *pw, *pkqv, *pvt, *ps;
    float *pb, *pss, *pr;
    cudaGetSymbolAddress((void**)&px,   h_x);
    cudaGetSymbolAddress((void**)&pw,   h_w);
    cudaGetSymbolAddress((void**)&pb,   g_bias);
    cudaGetSymbolAddress((void**)&pkqv, h_kqv);
    cudaGetSymbolAddress((void**)&pvt,  h_vt);
    cudaGetSymbolAddress((void**)&ps,   h_s);
    cudaGetSymbolAddress((void**)&pss,  g_sumsq);
    cudaGetSymbolAddress((void**)&pr,   g_rinv);

    const int smemB = 5 * (128 * 40 + 128 * 40) * 2;   // 102400 B
    cudaFuncSetAttribute(mma_gemm<0>, cudaFuncAttributeMaxDynamicSharedMemorySize, smemB);
    cudaFuncSetAttribute(mma_gemm<1>, cudaFuncAttributeMaxDynamicSharedMemorySize, smemB);
    cudaFuncSetAttribute(mma_gemm<2>, cudaFuncAttributeMaxDynamicSharedMemorySize, smemB);

    cudaMemsetAsync(pss, 0, G_ * sizeof(float));

    // fp32 -> fp16 conversions / packing
    f2h<<<(G_ * IND_ / 2 + 255) / 256, 256>>>(x, px, G_ * IND_ / 2);
    pack_w<<<(NP_ * IND_ / 2 + 255) / 256, 256>>>(Wk, Wq, Wv, pw);
    pack_bias<<<1, NP_>>>(bk, bq, bv, pb);

    // fused QKV projection: kqv = x @ [Wk;Wq;Wv]^T + [bk;bq;bv]
    mma_gemm<0><<<dim3(NP_ / 128, G_ / 128), 128, smemB>>>(
        px, pw, pb, nullptr, nullptr, pkqv, nullptr, nullptr,
        IND_, IND_, IND_, NP_, 0);

    // V^T for the NT big GEMM (V = kqv cols [256..768))
    transpose_h<<<dim3(OUTD_ / 32, G_ / 32), dim3(32, 8)>>>(pkqv + 2 * KQD_, NP_, pvt);

    // scores = k @ q^T (NT), fused row sum-of-squares
    mma_gemm<1><<<dim3(G_ / 128, G_ / 128), 128, smemB>>>(
        pkqv, pkqv + KQD_, nullptr, nullptr, nullptr, ps, nullptr, pss,
        KQD_, NP_, NP_, G_, 0);

    // rinv = 1 / max(||row||, eps)
    rinv_kernel<<<G_ / 256, 256>>>(pss, pr);

    // out = rinv[row] * (S @ V) + V   (NT against V^T, fp32 out)
    mma_gemm<2><<<dim3(OUTD_ / 128, G_ / 128), 128, smemB>>>(
        ps, pvt, nullptr, pkqv + 2 * KQD_, pr, nullptr, out, nullptr,
        G_, G_, G_, OUTD_, NP_);
}

// round 10
// speedup vs baseline: 1.9860x; 1.9860x over previous
#include <cuda_runtime.h>
#include <cuda_fp16.h>
#include <cstdint>
#include <cstddef>
#include <math.h>

#define G_    8192
#define IND_  512
#define KQD_  128
#define OUTD_ 512
#define NP_   768     // packed k|q|v columns
#define MTN_  640     // Mt columns = q(128) | v(512)
#define SPLITS_ 16

// ---------------- scratch (static __device__ = allowed) --------------------
__device__ __half h_x[(size_t)G_ * IND_];
__device__ __half h_w[(size_t)NP_ * IND_];        // packed [Wk;Wq;Wv] fp16
__device__ float  g_bias[NP_];                    // packed [bk;bq;bv]
__device__ __half h_kqv[(size_t)G_ * NP_];        // packed [k|q|v] fp16
__device__ float  g_part[(size_t)SPLITS_ * KQD_ * MTN_];  // split-K partials
__device__ float  g_gq[(size_t)KQD_ * KQD_];      // Gq = q^T q (fp32)
__device__ __half h_w2[(size_t)OUTD_ * 256];      // [o][0:128]=W^T hi, [128:256]=W^T lo
__device__ __half h_k2[(size_t)G_ * 256];         // [g][k | k] duplicated
__device__ float  g_sumsq[G_];
__device__ float  g_rinv[G_];

// ---------------- helpers ---------------------------------------------------
__device__ __forceinline__ uint32_t smem_u32(const void* p) {
    uint32_t a;
    asm("{ .reg .u64 t; cvta.to.shared.u64 t, %1; cvt.u32.u64 %0, t; }"
        : "=r"(a) : "l"(p));
    return a;
}
#define CP_ASYNC16(sm, gm) \
    asm volatile("cp.async.cg.shared.global [%0], [%1], 16;" :: "r"(sm), "l"(gm))
#define CP_COMMIT() asm volatile("cp.async.commit_group;" ::: "memory")
#define CP_WAIT(n)  asm volatile("cp.async.wait_group %0;" :: "n"(n) : "memory")

#define LDMX4(r0, r1, r2, r3, addr) \
    asm volatile("ldmatrix.sync.aligned.m8n8.x4.shared.b16 {%0,%1,%2,%3}, [%4];" \
                 : "=r"(r0), "=r"(r1), "=r"(r2), "=r"(r3) : "r"(addr))

__device__ __forceinline__ void mma_f16(float* c, const uint32_t* a, const uint32_t* b) {
    asm volatile(
        "mma.sync.aligned.m16n8k16.row.col.f32.f16.f16.f32 "
        "{%0,%1,%2,%3}, {%4,%5,%6,%7}, {%8,%9}, {%0,%1,%2,%3};"
        : "+f"(c[0]), "+f"(c[1]), "+f"(c[2]), "+f"(c[3])
        : "r"(a[0]), "r"(a[1]), "r"(a[2]), "r"(a[3]), "r"(b[0]), "r"(b[1]));
}

// ===========================================================================
// FP16 GEMM-NT:  C[M,N] = A[M,K] @ B[N,K]^T   (half, row-major, strided lds)
// Block 128x128, BK=32 halves, 4 warps, warp tile 64x64, 5-stage cp.async.
// MODE 0: Ch = h(acc + bias[col])
// MODE 2: Cf = rinv[row]*acc + float(aux_h[row*ldaux+col])
// ===========================================================================
template<int MODE>
__global__ void __launch_bounds__(128, 2)
mma_gemm(const __half* __restrict__ A, const __half* __restrict__ B,
         const float* __restrict__ aux_f, const __half* __restrict__ aux_h,
         const float* __restrict__ rinv,
         __half* __restrict__ Ch, float* __restrict__ Cf,
         int K, int lda, int ldb, int ldc, int ldaux)
{
    constexpr int STAGES = 5;
    constexpr int AS = 128 * 40;
    constexpr int BS = 128 * 40;

    extern __shared__ __half sm[];
    const uint32_t sAu = smem_u32(sm);
    const uint32_t sBu = smem_u32(sm + STAGES * AS);

    const int tid  = threadIdx.x;
    const int warp = tid >> 5;
    const int lane = tid & 31;
    const int gr   = lane >> 2;
    const int tc   = lane & 3;
    const int wm   = (warp & 1) * 64;
    const int wn   = (warp >> 1) * 64;
    const int rowBase = blockIdx.y * 128;
    const int colBase = blockIdx.x * 128;

    const int aRow  = wm + (lane & 15);
    const int aColH = (lane >> 4) << 3;
    const int bRow  = wn + ((lane >> 4) << 3) + (lane & 7);
    const int bColH = ((lane >> 3) & 1) << 3;

    float acc[4][8][4];
#pragma unroll
    for (int mi = 0; mi < 4; mi++)
#pragma unroll
        for (int ni = 0; ni < 8; ni++)
#pragma unroll
            for (int r = 0; r < 4; r++) acc[mi][ni][r] = 0.f;

    const int T = K / 32;

    auto load_stage = [&](int it, int buf) {
        const int k0 = it * 32;
#pragma unroll
        for (int l = 0; l < 4; l++) {
            int c = tid + l * 128;
            int r = c >> 2, ck = (c & 3) * 8;
            CP_ASYNC16(sAu + (uint32_t)(buf * AS + r * 40 + ck) * 2,
                       A + (size_t)(rowBase + r) * lda + k0 + ck);
        }
#pragma unroll
        for (int l = 0; l < 4; l++) {
            int c = tid + l * 128;
            int r = c >> 2, ck = (c & 3) * 8;
            CP_ASYNC16(sBu + (uint32_t)(buf * BS + r * 40 + ck) * 2,
                       B + (size_t)(colBase + r) * ldb + k0 + ck);
        }
        CP_COMMIT();
    };

#pragma unroll
    for (int s = 0; s < STAGES - 1; s++)
        if (s < T) load_stage(s, s);

    int buf = 0;
    for (int i = 0; i < T; i++) {
        const int rem = T - 1 - i;
        if (rem >= 3)      { CP_WAIT(3); }
        else if (rem == 2) { CP_WAIT(2); }
        else if (rem == 1) { CP_WAIT(1); }
        else               { CP_WAIT(0); }
        __syncthreads();
        if (i + STAGES - 1 < T) {
            int nb = buf + STAGES - 1; if (nb >= STAGES) nb -= STAGES;
            load_stage(i + STAGES - 1, nb);
        }

        const uint32_t cA = sAu + (uint32_t)(buf * AS) * 2;
        const uint32_t cB = sBu + (uint32_t)(buf * BS) * 2;
#pragma unroll
        for (int ks = 0; ks < 2; ks++) {
            const int kk = ks * 16;
            uint32_t a[4][4], b[8][2];
#pragma unroll
            for (int mi = 0; mi < 4; mi++) {
                uint32_t ad = cA + (uint32_t)((aRow + mi * 16) * 40 + kk + aColH) * 2;
                LDMX4(a[mi][0], a[mi][1], a[mi][2], a[mi][3], ad);
            }
#pragma unroll
            for (int p = 0; p < 4; p++) {
                uint32_t bd = cB + (uint32_t)((bRow + p * 16) * 40 + kk + bColH) * 2;
                LDMX4(b[2 * p][0], b[2 * p][1], b[2 * p + 1][0], b[2 * p + 1][1], bd);
            }
#pragma unroll
            for (int mi = 0; mi < 4; mi++)
#pragma unroll
                for (int ni = 0; ni < 8; ni++)
                    mma_f16(acc[mi][ni], a[mi], b[ni]);
        }
        buf++; if (buf >= STAGES) buf -= STAGES;
    }

#pragma unroll
    for (int mi = 0; mi < 4; mi++) {
#pragma unroll
        for (int h = 0; h < 2; h++) {
            const int row = rowBase + wm + mi * 16 + h * 8 + gr;
            float rv = 0.f;
            if (MODE == 2) rv = rinv[row];
#pragma unroll
            for (int ni = 0; ni < 8; ni++) {
                const int col = colBase + wn + ni * 8 + tc * 2;
                float v0 = acc[mi][ni][h * 2 + 0];
                float v1 = acc[mi][ni][h * 2 + 1];
                if (MODE == 0) {
                    __half2 o = __floats2half2_rn(v0 + aux_f[col], v1 + aux_f[col + 1]);
                    *reinterpret_cast<__half2*>(Ch + (size_t)row * ldc + col) = o;
                } else {
                    float2 res = __half22float2(
                        *reinterpret_cast<const __half2*>(aux_h + (size_t)row * ldaux + col));
                    float2 o;
                    o.x = rv * v0 + res.x;
                    o.y = rv * v1 + res.y;
                    *reinterpret_cast<float2*>(Cf + (size_t)row * ldc + col) = o;
                }
            }
        }
    }
}

// ===========================================================================
// Mt = q^T @ kqv[:,128:768]  ->  [128 x 640] = [Gq | W], split-K SIMT fp32.
// grid (10, 2, SPLITS), 256 thr, tile 64x64, K-chunk = G/SPLITS.
// ===========================================================================
__global__ void __launch_bounds__(256)
mt_splitk(const __half* __restrict__ kqv, float* __restrict__ part)
{
    __shared__ __half sQ[16][68];
    __shared__ __half sZ[16][68];

    const int tid = threadIdx.x;
    const int tx = tid & 15, ty = tid >> 4;
    const int n0 = blockIdx.x * 64;
    const int d0 = blockIdx.y * 64;
    const int g0 = blockIdx.z * (G_ / SPLITS_);

    float acc[4][4];
#pragma unroll
    for (int i = 0; i < 4; i++)
#pragma unroll
        for (int j = 0; j < 4; j++) acc[i][j] = 0.f;

    const int lr = tid >> 4;          // 0..15 load row
    const int lc = (tid & 15) * 4;    // 0..60 load col (halves)

    for (int kt = 0; kt < (G_ / SPLITS_) / 16; kt++) {
        const int g = g0 + kt * 16;
        *reinterpret_cast<uint2*>(&sQ[lr][lc]) =
            *reinterpret_cast<const uint2*>(kqv + (size_t)(g + lr) * NP_ + KQD_ + d0 + lc);
        *reinterpret_cast<uint2*>(&sZ[lr][lc]) =
            *reinterpret_cast<const uint2*>(kqv + (size_t)(g + lr) * NP_ + KQD_ + n0 + lc);
        __syncthreads();
#pragma unroll
        for (int kk = 0; kk < 16; kk++) {
            float af[4], bf[4];
#pragma unroll
            for (int i = 0; i < 4; i++) af[i] = __half2float(sQ[kk][ty * 4 + i]);
#pragma unroll
            for (int j = 0; j < 4; j++) bf[j] = __half2float(sZ[kk][tx * 4 + j]);
#pragma unroll
            for (int i = 0; i < 4; i++)
#pragma unroll
                for (int j = 0; j < 4; j++) acc[i][j] += af[i] * bf[j];
        }
        __syncthreads();
    }

    float* dst = part + (size_t)blockIdx.z * KQD_ * MTN_;
#pragma unroll
    for (int i = 0; i < 4; i++)
#pragma unroll
        for (int j = 0; j < 4; j++)
            dst[(size_t)(d0 + ty * 4 + i) * MTN_ + n0 + tx * 4 + j] = acc[i][j];
}

// reduce partials -> Gq fp32 [128,128] and h_w2 (W^T hi|lo fp16 [512,256])
__global__ void mt_reduce(const float* __restrict__ part,
                          float* __restrict__ Gq, __half* __restrict__ w2)
{
    int idx = blockIdx.x * 256 + threadIdx.x;      // over 128*640
    if (idx >= KQD_ * MTN_) return;
    int d = idx / MTN_, j = idx % MTN_;
    float s = 0.f;
#pragma unroll
    for (int z = 0; z < SPLITS_; z++)
        s += part[(size_t)z * KQD_ * MTN_ + idx];
    if (j < KQD_) {
        Gq[d * KQD_ + j] = s;
    } else {
        int o = j - KQD_;
        __half hi = __float2half_rn(s);
        w2[(size_t)o * 256 + d]        = hi;
        w2[(size_t)o * 256 + 128 + d]  = __float2half_rn(s - __half2float(hi));
    }
}

// k2[g] = [k_g | k_g]  (duplicate k cols for the K=256 hi+lo out GEMM)
__global__ void k2_copy(const __half* __restrict__ kqv, __half* __restrict__ k2)
{
    int idx = blockIdx.x * 256 + threadIdx.x;      // over 8192*16
    int g = idx >> 4, c8 = (idx & 15) * 8;
    uint4 v = *reinterpret_cast<const uint4*>(kqv + (size_t)g * NP_ + c8);
    *reinterpret_cast<uint4*>(k2 + (size_t)g * 256 + c8) = v;
    *reinterpret_cast<uint4*>(k2 + (size_t)g * 256 + 128 + c8) = v;
}

// sumsq_i = k_i Gq k_i^T (fp32, deterministic). 128 CTAs x 8 warps x 8 rows.
__global__ void __launch_bounds__(256)
sumsq_quad(const float* __restrict__ Gq, const __half* __restrict__ kqv,
           float* __restrict__ sumsq)
{
    extern __shared__ float smq[];        // [128*129] gq + [8*128] kf
    float* gq = smq;
    float* kf = smq + 128 * 129;

    const int tid = threadIdx.x;
    for (int i = tid; i < 128 * 128; i += 256)
        gq[(i >> 7) * 129 + (i & 127)] = Gq[i];
    __syncthreads();

    const int warp = tid >> 5, lane = tid & 31;
    float* kw = kf + warp * 128;

    for (int rr = 0; rr < 8; rr++) {
        int row = (blockIdx.x * 8 + warp) * 8 + rr;
        const __half2* src = reinterpret_cast<const __half2*>(kqv + (size_t)row * NP_);
        float2 v0 = __half22float2(src[lane * 2]);
        float2 v1 = __half22float2(src[lane * 2 + 1]);
        kw[lane * 4 + 0] = v0.x; kw[lane * 4 + 1] = v0.y;
        kw[lane * 4 + 2] = v1.x; kw[lane * 4 + 3] = v1.y;
        __syncwarp();
        float s = 0.f;
#pragma unroll
        for (int m = 0; m < 4; m++) {
            int a = lane + 32 * m;
            float inner = 0.f;
#pragma unroll 16
            for (int b = 0; b < 128; b++)
                inner += gq[a * 129 + b] * kw[b];
            s += kw[a] * inner;
        }
#pragma unroll
        for (int off = 16; off > 0; off >>= 1)
            s += __shfl_xor_sync(0xffffffffu, s, off);
        if (lane == 0) sumsq[row] = s;
        __syncwarp();
    }
}

__global__ void rinv_kernel(const float* __restrict__ ss, float* __restrict__ rinv)
{
    int i = blockIdx.x * 256 + threadIdx.x;
    float n = sqrtf(ss[i]);
    rinv[i] = 1.0f / fmaxf(n, 1e-12f);
}

// ---------------------------------------------------------------------------
__global__ void f2h(const float* __restrict__ in, __half* __restrict__ out, int n2)
{
    int i = blockIdx.x * 256 + threadIdx.x;
    if (i < n2) {
        float2 v = reinterpret_cast<const float2*>(in)[i];
        reinterpret_cast<__half2*>(out)[i] = __floats2half2_rn(v.x, v.y);
    }
}

__global__ void pack_w(const float* __restrict__ wk, const float* __restrict__ wq,
                       const float* __restrict__ wv, __half* __restrict__ out)
{
    int i = blockIdx.x * 256 + threadIdx.x;
    if (i >= NP_ * IND_ / 2) return;
    int row = i / (IND_ / 2);
    int c2  = i % (IND_ / 2);
    const float* src; int sr;
    if (row < KQD_)          { src = wk; sr = row; }
    else if (row < 2 * KQD_) { src = wq; sr = row - KQD_; }
    else                     { src = wv; sr = row - 2 * KQD_; }
    float2 v = reinterpret_cast<const float2*>(src + (size_t)sr * IND_)[c2];
    reinterpret_cast<__half2*>(out + (size_t)row * IND_)[c2] = __floats2half2_rn(v.x, v.y);
}

__global__ void pack_bias(const float* __restrict__ bk, const float* __restrict__ bq,
                          const float* __restrict__ bv, float* __restrict__ out)
{
    int i = threadIdx.x;
    if (i < KQD_)          out[i] = bk[i];
    else if (i < 2 * KQD_) out[i] = bq[i - KQD_];
    else                   out[i] = bv[i - 2 * KQD_];
}

// ---------------------------------------------------------------------------
extern "C" void kernel_launch(void* const* d_in, const int* in_sizes, int n_in,
                              void* d_out, int out_size)
{
    const float* x  = (const float*)d_in[0];
    const float* Wk = (const float*)d_in[1];
    const float* bk = (const float*)d_in[2];
    const float* Wq = (const float*)d_in[3];
    const float* bq = (const float*)d_in[4];
    const float* Wv = (const float*)d_in[5];
    const float* bv = (const float*)d_in[6];
    float* out = (float*)d_out;
    (void)in_sizes; (void)n_in; (void)out_size;

    __half *px, *pw, *pkqv, *pw2, *pk2;
    float *pb, *ppart, *pgq, *pss, *pr;
    cudaGetSymbolAddress((void**)&px,    h_x);
    cudaGetSymbolAddress((void**)&pw,    h_w);
    cudaGetSymbolAddress((void**)&pb,    g_bias);
    cudaGetSymbolAddress((void**)&pkqv,  h_kqv);
    cudaGetSymbolAddress((void**)&ppart, g_part);
    cudaGetSymbolAddress((void**)&pgq,   g_gq);
    cudaGetSymbolAddress((void**)&pw2,   h_w2);
    cudaGetSymbolAddress((void**)&pk2,   h_k2);
    cudaGetSymbolAddress((void**)&pss,   g_sumsq);
    cudaGetSymbolAddress((void**)&pr,    g_rinv);

    const int smemB = 5 * (128 * 40 + 128 * 40) * 2;   // 102400 B
    cudaFuncSetAttribute(mma_gemm<0>, cudaFuncAttributeMaxDynamicSharedMemorySize, smemB);
    cudaFuncSetAttribute(mma_gemm<2>, cudaFuncAttributeMaxDynamicSharedMemorySize, smemB);
    const int smemQ = (128 * 129 + 8 * 128) * 4;       // 70144 B
    cudaFuncSetAttribute(sumsq_quad, cudaFuncAttributeMaxDynamicSharedMemorySize, smemQ);

    // prep: fp32 -> fp16 conversions / packing
    f2h<<<(G_ * IND_ / 2 + 255) / 256, 256>>>(x, px, G_ * IND_ / 2);
    pack_w<<<(NP_ * IND_ / 2 + 255) / 256, 256>>>(Wk, Wq, Wv, pw);
    pack_bias<<<1, NP_>>>(bk, bq, bv, pb);

    // fused QKV projection: kqv = x @ [Wk;Wq;Wv]^T + bias
    mma_gemm<0><<<dim3(NP_ / 128, G_ / 128), 128, smemB>>>(
        px, pw, pb, nullptr, nullptr, pkqv, nullptr,
        IND_, IND_, IND_, NP_, 0);

    // Mt = q^T @ [q|v]  (split-K, fp32 partials, deterministic reduce)
    mt_splitk<<<dim3(MTN_ / 64, KQD_ / 64, SPLITS_), 256>>>(pkqv, ppart);
    mt_reduce<<<(KQD_ * MTN_ + 255) / 256, 256>>>(ppart, pgq, pw2);

    // k2 = [k | k] for the hi+lo W GEMM
    k2_copy<<<(G_ * 16 + 255) / 256, 256>>>(pkqv, pk2);

    // sumsq_i = k_i Gq k_i^T ; rinv
    sumsq_quad<<<128, 256, smemQ>>>(pgq, pkqv, pss);
    rinv_kernel<<<G_ / 256, 256>>>(pss, pr);

    // out = rinv[row] * (k @ W_hi + k @ W_lo) + v   (K=256 NT GEMM)
    mma_gemm<2><<<dim3(OUTD_ / 128, G_ / 128), 128, smemB>>>(
        pk2, pw2, nullptr, pkqv + 2 * KQD_, pr, nullptr, out,
        256, 256, 256, OUTD_, NP_);
}

// round 11
// speedup vs baseline: 3.4863x; 1.7554x over previous
#include <cuda_runtime.h>
#include <cuda_fp16.h>
#include <cstdint>
#include <cstddef>
#include <math.h>

#define G_    8192
#define IND_  512
#define KQD_  128
#define OUTD_ 512
#define NP_   768     // packed k|q|v columns
#define MTN_  640     // Mt columns = q(128) | v(512)
#define SPLITS_ 16

// ---------------- scratch (static __device__ = allowed) --------------------
__device__ __half h_x[(size_t)G_ * IND_];
__device__ __half h_w[(size_t)NP_ * IND_];        // packed [Wk;Wq;Wv] fp16
__device__ float  g_bias[NP_];                    // packed [bk;bq;bv]
__device__ __half h_kqv[(size_t)G_ * NP_];        // packed [k|q|v] fp16
__device__ __half h_zt[(size_t)MTN_ * G_];        // zT = (kqv[:,128:768])^T
__device__ float  g_part[(size_t)SPLITS_ * KQD_ * MTN_];  // split-K partials
__device__ __half h_b2[(size_t)MTN_ * 256];       // [W^T hi|lo ; Gq hi|lo]
__device__ __half h_k2[(size_t)G_ * 256];         // [g][k | k] duplicated
__device__ float  g_big[(size_t)G_ * MTN_];       // [U | y] fp32

// ---------------- helpers ---------------------------------------------------
__device__ __forceinline__ uint32_t smem_u32(const void* p) {
    uint32_t a;
    asm("{ .reg .u64 t; cvta.to.shared.u64 t, %1; cvt.u32.u64 %0, t; }"
        : "=r"(a) : "l"(p));
    return a;
}
#define CP_ASYNC16(sm, gm) \
    asm volatile("cp.async.cg.shared.global [%0], [%1], 16;" :: "r"(sm), "l"(gm))
#define CP_COMMIT() asm volatile("cp.async.commit_group;" ::: "memory")
#define CP_WAIT(n)  asm volatile("cp.async.wait_group %0;" :: "n"(n) : "memory")

#define LDMX4(r0, r1, r2, r3, addr) \
    asm volatile("ldmatrix.sync.aligned.m8n8.x4.shared.b16 {%0,%1,%2,%3}, [%4];" \
                 : "=r"(r0), "=r"(r1), "=r"(r2), "=r"(r3) : "r"(addr))

__device__ __forceinline__ void mma_f16(float* c, const uint32_t* a, const uint32_t* b) {
    asm volatile(
        "mma.sync.aligned.m16n8k16.row.col.f32.f16.f16.f32 "
        "{%0,%1,%2,%3}, {%4,%5,%6,%7}, {%8,%9}, {%0,%1,%2,%3};"
        : "+f"(c[0]), "+f"(c[1]), "+f"(c[2]), "+f"(c[3])
        : "r"(a[0]), "r"(a[1]), "r"(a[2]), "r"(a[3]), "r"(b[0]), "r"(b[1]));
}

// ===========================================================================
// FP16 GEMM-NT:  C[M,N] = A[M,K_total] @ B[N,K_total]^T  (half, row-major)
// Block 128x128, BK=32 halves, 4 warps, warp tile 64x64, 5-stage cp.async.
// Split-K aware: this launch covers K elems starting at blockIdx.z*K,
// output goes to (Cf + blockIdx.z*pstride)   [MODE 3]
// MODE 0: Ch = h(acc + bias[col])   (proj; single z-slice)
// MODE 3: Cf = acc (fp32)
// ===========================================================================
template<int MODE>
__global__ void __launch_bounds__(128, 2)
mma_gemm(const __half* __restrict__ A, const __half* __restrict__ B,
         const float* __restrict__ aux_f,
         __half* __restrict__ Ch, float* __restrict__ Cf,
         int K, int lda, int ldb, int ldc, int pstride)
{
    constexpr int STAGES = 5;
    constexpr int AS = 128 * 40;
    constexpr int BS = 128 * 40;

    extern __shared__ __half sm[];
    const uint32_t sAu = smem_u32(sm);
    const uint32_t sBu = smem_u32(sm + STAGES * AS);

    const int tid  = threadIdx.x;
    const int warp = tid >> 5;
    const int lane = tid & 31;
    const int gr   = lane >> 2;
    const int tc   = lane & 3;
    const int wm   = (warp & 1) * 64;
    const int wn   = (warp >> 1) * 64;
    const int rowBase = blockIdx.y * 128;
    const int colBase = blockIdx.x * 128;
    const int kbase   = blockIdx.z * K;

    const int aRow  = wm + (lane & 15);
    const int aColH = (lane >> 4) << 3;
    const int bRow  = wn + ((lane >> 4) << 3) + (lane & 7);
    const int bColH = ((lane >> 3) & 1) << 3;

    float acc[4][8][4];
#pragma unroll
    for (int mi = 0; mi < 4; mi++)
#pragma unroll
        for (int ni = 0; ni < 8; ni++)
#pragma unroll
            for (int r = 0; r < 4; r++) acc[mi][ni][r] = 0.f;

    const int T = K / 32;

    auto load_stage = [&](int it, int buf) {
        const int k0 = kbase + it * 32;
#pragma unroll
        for (int l = 0; l < 4; l++) {
            int c = tid + l * 128;
            int r = c >> 2, ck = (c & 3) * 8;
            CP_ASYNC16(sAu + (uint32_t)(buf * AS + r * 40 + ck) * 2,
                       A + (size_t)(rowBase + r) * lda + k0 + ck);
        }
#pragma unroll
        for (int l = 0; l < 4; l++) {
            int c = tid + l * 128;
            int r = c >> 2, ck = (c & 3) * 8;
            CP_ASYNC16(sBu + (uint32_t)(buf * BS + r * 40 + ck) * 2,
                       B + (size_t)(colBase + r) * ldb + k0 + ck);
        }
        CP_COMMIT();
    };

#pragma unroll
    for (int s = 0; s < STAGES - 1; s++)
        if (s < T) load_stage(s, s);

    int buf = 0;
    for (int i = 0; i < T; i++) {
        const int rem = T - 1 - i;
        if (rem >= 3)      { CP_WAIT(3); }
        else if (rem == 2) { CP_WAIT(2); }
        else if (rem == 1) { CP_WAIT(1); }
        else               { CP_WAIT(0); }
        __syncthreads();
        if (i + STAGES - 1 < T) {
            int nb = buf + STAGES - 1; if (nb >= STAGES) nb -= STAGES;
            load_stage(i + STAGES - 1, nb);
        }

        const uint32_t cA = sAu + (uint32_t)(buf * AS) * 2;
        const uint32_t cB = sBu + (uint32_t)(buf * BS) * 2;
#pragma unroll
        for (int ks = 0; ks < 2; ks++) {
            const int kk = ks * 16;
            uint32_t a[4][4], b[8][2];
#pragma unroll
            for (int mi = 0; mi < 4; mi++) {
                uint32_t ad = cA + (uint32_t)((aRow + mi * 16) * 40 + kk + aColH) * 2;
                LDMX4(a[mi][0], a[mi][1], a[mi][2], a[mi][3], ad);
            }
#pragma unroll
            for (int p = 0; p < 4; p++) {
                uint32_t bd = cB + (uint32_t)((bRow + p * 16) * 40 + kk + bColH) * 2;
                LDMX4(b[2 * p][0], b[2 * p][1], b[2 * p + 1][0], b[2 * p + 1][1], bd);
            }
#pragma unroll
            for (int mi = 0; mi < 4; mi++)
#pragma unroll
                for (int ni = 0; ni < 8; ni++)
                    mma_f16(acc[mi][ni], a[mi], b[ni]);
        }
        buf++; if (buf >= STAGES) buf -= STAGES;
    }

    float* Cfo = Cf + (size_t)blockIdx.z * pstride;
#pragma unroll
    for (int mi = 0; mi < 4; mi++) {
#pragma unroll
        for (int h = 0; h < 2; h++) {
            const int row = rowBase + wm + mi * 16 + h * 8 + gr;
#pragma unroll
            for (int ni = 0; ni < 8; ni++) {
                const int col = colBase + wn + ni * 8 + tc * 2;
                float v0 = acc[mi][ni][h * 2 + 0];
                float v1 = acc[mi][ni][h * 2 + 1];
                if (MODE == 0) {
                    __half2 o = __floats2half2_rn(v0 + aux_f[col], v1 + aux_f[col + 1]);
                    *reinterpret_cast<__half2*>(Ch + (size_t)row * ldc + col) = o;
                } else {
                    float2 o; o.x = v0; o.y = v1;
                    *reinterpret_cast<float2*>(Cfo + (size_t)row * ldc + col) = o;
                }
            }
        }
    }
}

// ---------------------------------------------------------------------------
__global__ void f2h(const float* __restrict__ in, __half* __restrict__ out, int n2)
{
    int i = blockIdx.x * 256 + threadIdx.x;
    if (i < n2) {
        float2 v = reinterpret_cast<const float2*>(in)[i];
        reinterpret_cast<__half2*>(out)[i] = __floats2half2_rn(v.x, v.y);
    }
}

__global__ void pack_w(const float* __restrict__ wk, const float* __restrict__ wq,
                       const float* __restrict__ wv, __half* __restrict__ out)
{
    int i = blockIdx.x * 256 + threadIdx.x;
    if (i >= NP_ * IND_ / 2) return;
    int row = i / (IND_ / 2);
    int c2  = i % (IND_ / 2);
    const float* src; int sr;
    if (row < KQD_)          { src = wk; sr = row; }
    else if (row < 2 * KQD_) { src = wq; sr = row - KQD_; }
    else                     { src = wv; sr = row - 2 * KQD_; }
    float2 v = reinterpret_cast<const float2*>(src + (size_t)sr * IND_)[c2];
    reinterpret_cast<__half2*>(out + (size_t)row * IND_)[c2] = __floats2half2_rn(v.x, v.y);
}

__global__ void pack_bias(const float* __restrict__ bk, const float* __restrict__ bq,
                          const float* __restrict__ bv, float* __restrict__ out)
{
    int i = threadIdx.x;
    if (i < KQD_)          out[i] = bk[i];
    else if (i < 2 * KQD_) out[i] = bq[i - KQD_];
    else                   out[i] = bv[i - 2 * KQD_];
}

// generic 32x32 fp16 transpose: out[x][y] = in[y][x]
__global__ void transpose_g(const __half* __restrict__ in, int ldin,
                            __half* __restrict__ out, int ldout)
{
    __shared__ __half t[32][33];
    int x  = blockIdx.x * 32 + threadIdx.x;
    int y0 = blockIdx.y * 32;
#pragma unroll
    for (int i = threadIdx.y; i < 32; i += 8)
        t[i][threadIdx.x] = in[(size_t)(y0 + i) * ldin + x];
    __syncthreads();
    int ox  = y0 + threadIdx.x;
    int oy0 = blockIdx.x * 32;
#pragma unroll
    for (int i = threadIdx.y; i < 32; i += 8)
        out[(size_t)(oy0 + i) * ldout + ox] = t[threadIdx.x][i];
}

// reduce split-K partials -> B2 [640x256] fp16 hi|lo
// Mt[d][j]: j<128 -> Gq col j  => B2 row 512+j ;  j>=128 -> W col o=j-128 => B2 row o
__global__ void mt_reduce(const float* __restrict__ part, __half* __restrict__ b2)
{
    int idx = blockIdx.x * 256 + threadIdx.x;      // over 128*640
    if (idx >= KQD_ * MTN_) return;
    int d = idx / MTN_, j = idx % MTN_;
    float s = 0.f;
#pragma unroll
    for (int z = 0; z < SPLITS_; z++)
        s += part[(size_t)z * KQD_ * MTN_ + idx];
    int r = (j < KQD_) ? (512 + j) : (j - KQD_);
    __half hi = __float2half_rn(s);
    b2[(size_t)r * 256 + d]       = hi;
    b2[(size_t)r * 256 + 128 + d] = __float2half_rn(s - __half2float(hi));
}

// k2[g] = [k_g | k_g]
__global__ void k2_copy(const __half* __restrict__ kqv, __half* __restrict__ k2)
{
    int idx = blockIdx.x * 256 + threadIdx.x;      // over 8192*16
    int g = idx >> 4, c8 = (idx & 15) * 8;
    uint4 v = *reinterpret_cast<const uint4*>(kqv + (size_t)g * NP_ + c8);
    *reinterpret_cast<uint4*>(k2 + (size_t)g * 256 + c8) = v;
    *reinterpret_cast<uint4*>(k2 + (size_t)g * 256 + 128 + c8) = v;
}

// rowwise tail: sumsq = y.k ; rinv ; out = rinv*U + v
__global__ void __launch_bounds__(256)
epilogue(const float* __restrict__ big, const __half* __restrict__ kqv,
         float* __restrict__ out)
{
    const int row  = blockIdx.x * 8 + (threadIdx.x >> 5);
    const int lane = threadIdx.x & 31;
    const float* rowp = big + (size_t)row * MTN_;

    float s = 0.f;
#pragma unroll
    for (int m = 0; m < 4; m++) {
        int d = lane + 32 * m;
        s += rowp[512 + d] * __half2float(kqv[(size_t)row * NP_ + d]);
    }
#pragma unroll
    for (int off = 16; off > 0; off >>= 1)
        s += __shfl_xor_sync(0xffffffffu, s, off);
    const float rinv = 1.0f / fmaxf(sqrtf(s), 1e-12f);

    const __half2* vp = reinterpret_cast<const __half2*>(kqv + (size_t)row * NP_ + 2 * KQD_);
#pragma unroll
    for (int m = 0; m < 8; m++) {
        int o2 = lane + 32 * m;
        float2 u = *reinterpret_cast<const float2*>(rowp + o2 * 2);
        float2 v = __half22float2(vp[o2]);
        float2 r;
        r.x = rinv * u.x + v.x;
        r.y = rinv * u.y + v.y;
        *reinterpret_cast<float2*>(out + (size_t)row * OUTD_ + o2 * 2) = r;
    }
}

// ---------------------------------------------------------------------------
extern "C" void kernel_launch(void* const* d_in, const int* in_sizes, int n_in,
                              void* d_out, int out_size)
{
    const float* x  = (const float*)d_in[0];
    const float* Wk = (const float*)d_in[1];
    const float* bk = (const float*)d_in[2];
    const float* Wq = (const float*)d_in[3];
    const float* bq = (const float*)d_in[4];
    const float* Wv = (const float*)d_in[5];
    const float* bv = (const float*)d_in[6];
    float* out = (float*)d_out;
    (void)in_sizes; (void)n_in; (void)out_size;

    __half *px, *pw, *pkqv, *pzt, *pb2, *pk2;
    float *pb, *ppart, *pbig;
    cudaGetSymbolAddress((void**)&px,    h_x);
    cudaGetSymbolAddress((void**)&pw,    h_w);
    cudaGetSymbolAddress((void**)&pb,    g_bias);
    cudaGetSymbolAddress((void**)&pkqv,  h_kqv);
    cudaGetSymbolAddress((void**)&pzt,   h_zt);
    cudaGetSymbolAddress((void**)&ppart, g_part);
    cudaGetSymbolAddress((void**)&pb2,   h_b2);
    cudaGetSymbolAddress((void**)&pk2,   h_k2);
    cudaGetSymbolAddress((void**)&pbig,  g_big);

    const int smemB = 5 * (128 * 40 + 128 * 40) * 2;   // 102400 B
    cudaFuncSetAttribute(mma_gemm<0>, cudaFuncAttributeMaxDynamicSharedMemorySize, smemB);
    cudaFuncSetAttribute(mma_gemm<3>, cudaFuncAttributeMaxDynamicSharedMemorySize, smemB);

    // prep: fp32 -> fp16 conversions / packing
    f2h<<<(G_ * IND_ / 2 + 255) / 256, 256>>>(x, px, G_ * IND_ / 2);
    pack_w<<<(NP_ * IND_ / 2 + 255) / 256, 256>>>(Wk, Wq, Wv, pw);
    pack_bias<<<1, NP_>>>(bk, bq, bv, pb);

    // fused QKV projection: kqv = x @ [Wk;Wq;Wv]^T + bias
    mma_gemm<0><<<dim3(NP_ / 128, G_ / 128), 128, smemB>>>(
        px, pw, pb, pkqv, nullptr, IND_, IND_, IND_, NP_, 0);

    // zT = (kqv[:,128:768])^T  [640 x 8192]
    transpose_g<<<dim3(MTN_ / 32, G_ / 32), dim3(32, 8)>>>(pkqv + KQD_, NP_, pzt, G_);

    // k2 = [k | k]
    k2_copy<<<(G_ * 16) / 256, 256>>>(pkqv, pk2);

    // Mt = q^T @ [q|v] : NT GEMM A = zT[0:128], B = zT, split-K 16 x 512
    mma_gemm<3><<<dim3(MTN_ / 128, 1, SPLITS_), 128, smemB>>>(
        pzt, pzt, nullptr, nullptr, ppart, G_ / SPLITS_, G_, G_, MTN_, KQD_ * MTN_);
    mt_reduce<<<(KQD_ * MTN_ + 255) / 256, 256>>>(ppart, pb2);

    // big = k2 @ B2^T  ->  [U | y] fp32 [8192 x 640]
    mma_gemm<3><<<dim3(MTN_ / 128, G_ / 128, 1), 128, smemB>>>(
        pk2, pb2, nullptr, nullptr, pbig, 256, 256, 256, MTN_, 0);

    // rowwise: sumsq = y.k ; rinv ; out = rinv*U + v
    epilogue<<<G_ / 8, 256>>>(pbig, pkqv, out);
}

// round 12
// speedup vs baseline: 3.9727x; 1.1395x over previous
#include <cuda_runtime.h>
#include <cuda_fp16.h>
#include <cstdint>
#include <cstddef>
#include <math.h>

#define G_    8192
#define IND_  512
#define KQD_  128
#define OUTD_ 512
#define NP_   768     // packed k|q|v columns
#define MTN_  640     // Mt columns = q(128) | v(512)
#define SPLITS_ 16

// ---------------- scratch (static __device__ = allowed) --------------------
__device__ __half h_x[(size_t)G_ * IND_];
__device__ __half h_w[(size_t)NP_ * IND_];        // packed [Wk;Wq;Wv] fp16
__device__ float  g_bias[NP_];                    // packed [bk;bq;bv]
__device__ __half h_kqv[(size_t)G_ * NP_];        // packed [k|q|v] fp16
__device__ float  g_part[(size_t)SPLITS_ * KQD_ * MTN_];  // split-K partials
__device__ __half h_b2[(size_t)MTN_ * 256];       // [W^T hi|lo ; Gq hi|lo]
__device__ __half h_k2[(size_t)G_ * 256];         // [g][k | k] (written by proj)
__device__ float  g_big[(size_t)G_ * MTN_];       // [U | y] fp32

// ---------------- helpers ---------------------------------------------------
__device__ __forceinline__ uint32_t smem_u32(const void* p) {
    uint32_t a;
    asm("{ .reg .u64 t; cvta.to.shared.u64 t, %1; cvt.u32.u64 %0, t; }"
        : "=r"(a) : "l"(p));
    return a;
}
#define CP_ASYNC16(sm, gm) \
    asm volatile("cp.async.cg.shared.global [%0], [%1], 16;" :: "r"(sm), "l"(gm))
#define CP_COMMIT() asm volatile("cp.async.commit_group;" ::: "memory")
#define CP_WAIT(n)  asm volatile("cp.async.wait_group %0;" :: "n"(n) : "memory")

#define LDMX4(r0, r1, r2, r3, addr) \
    asm volatile("ldmatrix.sync.aligned.m8n8.x4.shared.b16 {%0,%1,%2,%3}, [%4];" \
                 : "=r"(r0), "=r"(r1), "=r"(r2), "=r"(r3) : "r"(addr))

#define LDMX4T(r0, r1, r2, r3, addr) \
    asm volatile("ldmatrix.sync.aligned.m8n8.x4.trans.shared.b16 {%0,%1,%2,%3}, [%4];" \
                 : "=r"(r0), "=r"(r1), "=r"(r2), "=r"(r3) : "r"(addr))

__device__ __forceinline__ void mma_f16(float* c, const uint32_t* a, const uint32_t* b) {
    asm volatile(
        "mma.sync.aligned.m16n8k16.row.col.f32.f16.f16.f32 "
        "{%0,%1,%2,%3}, {%4,%5,%6,%7}, {%8,%9}, {%0,%1,%2,%3};"
        : "+f"(c[0]), "+f"(c[1]), "+f"(c[2]), "+f"(c[3])
        : "r"(a[0]), "r"(a[1]), "r"(a[2]), "r"(a[3]), "r"(b[0]), "r"(b[1]));
}

// ===========================================================================
// FP16 GEMM-NT:  C[M,N] = A[M,K] @ B[N,K]^T  (half, row-major)
// Block 128x128, BK=32 halves, 4 warps, warp tile 64x64, 5-stage cp.async.
// MODE 0: Ch = h(acc + bias[col]); if colBase==0 also write k2[row][col,+128]
// MODE 3: Cf = acc (fp32)
// ===========================================================================
template<int MODE>
__global__ void __launch_bounds__(128, 2)
mma_gemm(const __half* __restrict__ A, const __half* __restrict__ B,
         const float* __restrict__ aux_f,
         __half* __restrict__ Ch, float* __restrict__ Cf,
         __half* __restrict__ k2,
         int K, int lda, int ldb, int ldc)
{
    constexpr int STAGES = 5;
    constexpr int AS = 128 * 40;
    constexpr int BS = 128 * 40;

    extern __shared__ __half sm[];
    const uint32_t sAu = smem_u32(sm);
    const uint32_t sBu = smem_u32(sm + STAGES * AS);

    const int tid  = threadIdx.x;
    const int warp = tid >> 5;
    const int lane = tid & 31;
    const int gr   = lane >> 2;
    const int tc   = lane & 3;
    const int wm   = (warp & 1) * 64;
    const int wn   = (warp >> 1) * 64;
    const int rowBase = blockIdx.y * 128;
    const int colBase = blockIdx.x * 128;

    const int aRow  = wm + (lane & 15);
    const int aColH = (lane >> 4) << 3;
    const int bRow  = wn + ((lane >> 4) << 3) + (lane & 7);
    const int bColH = ((lane >> 3) & 1) << 3;

    float acc[4][8][4];
#pragma unroll
    for (int mi = 0; mi < 4; mi++)
#pragma unroll
        for (int ni = 0; ni < 8; ni++)
#pragma unroll
            for (int r = 0; r < 4; r++) acc[mi][ni][r] = 0.f;

    const int T = K / 32;

    auto load_stage = [&](int it, int buf) {
        const int k0 = it * 32;
#pragma unroll
        for (int l = 0; l < 4; l++) {
            int c = tid + l * 128;
            int r = c >> 2, ck = (c & 3) * 8;
            CP_ASYNC16(sAu + (uint32_t)(buf * AS + r * 40 + ck) * 2,
                       A + (size_t)(rowBase + r) * lda + k0 + ck);
        }
#pragma unroll
        for (int l = 0; l < 4; l++) {
            int c = tid + l * 128;
            int r = c >> 2, ck = (c & 3) * 8;
            CP_ASYNC16(sBu + (uint32_t)(buf * BS + r * 40 + ck) * 2,
                       B + (size_t)(colBase + r) * ldb + k0 + ck);
        }
        CP_COMMIT();
    };

#pragma unroll
    for (int s = 0; s < STAGES - 1; s++)
        if (s < T) load_stage(s, s);

    int buf = 0;
    for (int i = 0; i < T; i++) {
        const int rem = T - 1 - i;
        if (rem >= 3)      { CP_WAIT(3); }
        else if (rem == 2) { CP_WAIT(2); }
        else if (rem == 1) { CP_WAIT(1); }
        else               { CP_WAIT(0); }
        __syncthreads();
        if (i + STAGES - 1 < T) {
            int nb = buf + STAGES - 1; if (nb >= STAGES) nb -= STAGES;
            load_stage(i + STAGES - 1, nb);
        }

        const uint32_t cA = sAu + (uint32_t)(buf * AS) * 2;
        const uint32_t cB = sBu + (uint32_t)(buf * BS) * 2;
#pragma unroll
        for (int ks = 0; ks < 2; ks++) {
            const int kk = ks * 16;
            uint32_t a[4][4], b[8][2];
#pragma unroll
            for (int mi = 0; mi < 4; mi++) {
                uint32_t ad = cA + (uint32_t)((aRow + mi * 16) * 40 + kk + aColH) * 2;
                LDMX4(a[mi][0], a[mi][1], a[mi][2], a[mi][3], ad);
            }
#pragma unroll
            for (int p = 0; p < 4; p++) {
                uint32_t bd = cB + (uint32_t)((bRow + p * 16) * 40 + kk + bColH) * 2;
                LDMX4(b[2 * p][0], b[2 * p][1], b[2 * p + 1][0], b[2 * p + 1][1], bd);
            }
#pragma unroll
            for (int mi = 0; mi < 4; mi++)
#pragma unroll
                for (int ni = 0; ni < 8; ni++)
                    mma_f16(acc[mi][ni], a[mi], b[ni]);
        }
        buf++; if (buf >= STAGES) buf -= STAGES;
    }

#pragma unroll
    for (int mi = 0; mi < 4; mi++) {
#pragma unroll
        for (int h = 0; h < 2; h++) {
            const int row = rowBase + wm + mi * 16 + h * 8 + gr;
#pragma unroll
            for (int ni = 0; ni < 8; ni++) {
                const int col = colBase + wn + ni * 8 + tc * 2;
                float v0 = acc[mi][ni][h * 2 + 0];
                float v1 = acc[mi][ni][h * 2 + 1];
                if (MODE == 0) {
                    __half2 o = __floats2half2_rn(v0 + aux_f[col], v1 + aux_f[col + 1]);
                    *reinterpret_cast<__half2*>(Ch + (size_t)row * ldc + col) = o;
                    if (colBase == 0) {   // k columns -> duplicate into k2
                        *reinterpret_cast<__half2*>(k2 + (size_t)row * 256 + col) = o;
                        *reinterpret_cast<__half2*>(k2 + (size_t)row * 256 + 128 + col) = o;
                    }
                } else {
                    float2 o; o.x = v0; o.y = v1;
                    *reinterpret_cast<float2*>(Cf + (size_t)row * ldc + col) = o;
                }
            }
        }
    }
}

// ===========================================================================
// TN split-K GEMM: part[z][d][j] = sum_{g in slice z} kqv[g][128+d] * kqv[g][128+j]
// M=128 (d), N=640 (j, tiled 128), K=G split 16 ways.
// smem tiles [32 g][136 halves]; fragments via ldmatrix.x4.trans.
// ===========================================================================
__global__ void __launch_bounds__(128, 2)
mt_tn(const __half* __restrict__ kqv, float* __restrict__ part)
{
    constexpr int STAGES = 4;
    constexpr int TS = 32 * 136;          // halves per tile stage

    extern __shared__ __half sm[];
    const uint32_t sAu = smem_u32(sm);
    const uint32_t sBu = smem_u32(sm + STAGES * TS);

    const int tid  = threadIdx.x;
    const int warp = tid >> 5;
    const int lane = tid & 31;
    const int gr   = lane >> 2;
    const int tc   = lane & 3;
    const int wm   = (warp & 1) * 64;
    const int wn   = (warp >> 1) * 64;
    const int n0   = blockIdx.x * 128;
    const int zb   = blockIdx.z * (G_ / SPLITS_);

    // trans-ldmatrix selects
    const int aKr = ((lane >> 4) << 3) + (lane & 7);   // A: k-row within 16
    const int aMc = ((lane >> 3) & 1) << 3;            // A: m-col 0/8
    const int bKr = (((lane >> 3) & 1) << 3) + (lane & 7);
    const int bNc = (lane >> 4) << 3;

    float acc[4][8][4];
#pragma unroll
    for (int mi = 0; mi < 4; mi++)
#pragma unroll
        for (int ni = 0; ni < 8; ni++)
#pragma unroll
            for (int r = 0; r < 4; r++) acc[mi][ni][r] = 0.f;

    const int T = (G_ / SPLITS_) / 32;    // 16

    auto load_stage = [&](int it, int buf) {
        const int g0 = zb + it * 32;
#pragma unroll
        for (int l = 0; l < 4; l++) {
            int c = tid + l * 128;
            int gro = c >> 4, gc = (c & 15) * 8;      // 16 chunks per 128-half row
            CP_ASYNC16(sAu + (uint32_t)(buf * TS + gro * 136 + gc) * 2,
                       kqv + (size_t)(g0 + gro) * NP_ + KQD_ + gc);
        }
#pragma unroll
        for (int l = 0; l < 4; l++) {
            int c = tid + l * 128;
            int gro = c >> 4, gc = (c & 15) * 8;
            CP_ASYNC16(sBu + (uint32_t)(buf * TS + gro * 136 + gc) * 2,
                       kqv + (size_t)(g0 + gro) * NP_ + KQD_ + n0 + gc);
        }
        CP_COMMIT();
    };

#pragma unroll
    for (int s = 0; s < STAGES - 1; s++)
        load_stage(s, s);

    int buf = 0;
    for (int i = 0; i < T; i++) {
        const int rem = T - 1 - i;
        if (rem >= 2)      { CP_WAIT(2); }
        else if (rem == 1) { CP_WAIT(1); }
        else               { CP_WAIT(0); }
        __syncthreads();
        if (i + STAGES - 1 < T) {
            int nb = buf + STAGES - 1; if (nb >= STAGES) nb -= STAGES;
            load_stage(i + STAGES - 1, nb);
        }

        const uint32_t cA = sAu + (uint32_t)(buf * TS) * 2;
        const uint32_t cB = sBu + (uint32_t)(buf * TS) * 2;
#pragma unroll
        for (int ks = 0; ks < 2; ks++) {
            const int kk = ks * 16;
            uint32_t a[4][4], b[8][2];
#pragma unroll
            for (int mi = 0; mi < 4; mi++) {
                uint32_t ad = cA + (uint32_t)((kk + aKr) * 136 + wm + mi * 16 + aMc) * 2;
                LDMX4T(a[mi][0], a[mi][1], a[mi][2], a[mi][3], ad);
            }
#pragma unroll
            for (int p = 0; p < 4; p++) {
                uint32_t bd = cB + (uint32_t)((kk + bKr) * 136 + wn + p * 16 + bNc) * 2;
                LDMX4T(b[2 * p][0], b[2 * p][1], b[2 * p + 1][0], b[2 * p + 1][1], bd);
            }
#pragma unroll
            for (int mi = 0; mi < 4; mi++)
#pragma unroll
                for (int ni = 0; ni < 8; ni++)
                    mma_f16(acc[mi][ni], a[mi], b[ni]);
        }
        buf++; if (buf >= STAGES) buf -= STAGES;
    }

    float* dst = part + (size_t)blockIdx.z * KQD_ * MTN_;
#pragma unroll
    for (int mi = 0; mi < 4; mi++)
#pragma unroll
        for (int h = 0; h < 2; h++) {
            const int d = wm + mi * 16 + h * 8 + gr;
#pragma unroll
            for (int ni = 0; ni < 8; ni++) {
                const int col = n0 + wn + ni * 8 + tc * 2;
                float2 o;
                o.x = acc[mi][ni][h * 2 + 0];
                o.y = acc[mi][ni][h * 2 + 1];
                *reinterpret_cast<float2*>(dst + (size_t)d * MTN_ + col) = o;
            }
        }
}

// ---------------------------------------------------------------------------
// one prep kernel: x->fp16, pack W fp16, pack bias
__global__ void prep(const float* __restrict__ x,
                     const float* __restrict__ wk, const float* __restrict__ wq,
                     const float* __restrict__ wv,
                     const float* __restrict__ bk, const float* __restrict__ bq,
                     const float* __restrict__ bv,
                     __half* __restrict__ hx, __half* __restrict__ hw,
                     float* __restrict__ gb)
{
    const int NX = G_ * IND_ / 2;
    const int NW = NP_ * IND_ / 2;
    int i = blockIdx.x * 256 + threadIdx.x;
    if (i < NX) {
        float2 v = reinterpret_cast<const float2*>(x)[i];
        reinterpret_cast<__half2*>(hx)[i] = __floats2half2_rn(v.x, v.y);
    } else if (i < NX + NW) {
        int j = i - NX;
        int row = j / (IND_ / 2), c2 = j % (IND_ / 2);
        const float* src; int sr;
        if (row < KQD_)          { src = wk; sr = row; }
        else if (row < 2 * KQD_) { src = wq; sr = row - KQD_; }
        else                     { src = wv; sr = row - 2 * KQD_; }
        float2 v = reinterpret_cast<const float2*>(src + (size_t)sr * IND_)[c2];
        reinterpret_cast<__half2*>(hw + (size_t)row * IND_)[c2] = __floats2half2_rn(v.x, v.y);
    } else if (i < NX + NW + NP_) {
        int j = i - NX - NW;
        gb[j] = (j < KQD_) ? bk[j] : (j < 2 * KQD_) ? bq[j - KQD_] : bv[j - 2 * KQD_];
    }
}

// reduce split-K partials -> B2 [640x256] fp16 hi|lo
__global__ void mt_reduce(const float* __restrict__ part, __half* __restrict__ b2)
{
    int idx = blockIdx.x * 256 + threadIdx.x;
    if (idx >= KQD_ * MTN_) return;
    int d = idx / MTN_, j = idx % MTN_;
    float s = 0.f;
#pragma unroll
    for (int z = 0; z < SPLITS_; z++)
        s += part[(size_t)z * KQD_ * MTN_ + idx];
    int r = (j < KQD_) ? (512 + j) : (j - KQD_);
    __half hi = __float2half_rn(s);
    b2[(size_t)r * 256 + d]       = hi;
    b2[(size_t)r * 256 + 128 + d] = __float2half_rn(s - __half2float(hi));
}

// rowwise tail: sumsq = y.k ; rinv ; out = rinv*U + v
__global__ void __launch_bounds__(256)
epilogue(const float* __restrict__ big, const __half* __restrict__ kqv,
         float* __restrict__ out)
{
    const int row  = blockIdx.x * 8 + (threadIdx.x >> 5);
    const int lane = threadIdx.x & 31;
    const float* rowp = big + (size_t)row * MTN_;

    float s = 0.f;
    {
        float4 y = *reinterpret_cast<const float4*>(rowp + 512 + lane * 4);
        const __half2* kp = reinterpret_cast<const __half2*>(kqv + (size_t)row * NP_);
        float2 k0 = __half22float2(kp[lane * 2]);
        float2 k1 = __half22float2(kp[lane * 2 + 1]);
        s = y.x * k0.x + y.y * k0.y + y.z * k1.x + y.w * k1.y;
    }
#pragma unroll
    for (int off = 16; off > 0; off >>= 1)
        s += __shfl_xor_sync(0xffffffffu, s, off);
    const float rinv = 1.0f / fmaxf(sqrtf(s), 1e-12f);

    const __half2* vp = reinterpret_cast<const __half2*>(kqv + (size_t)row * NP_ + 2 * KQD_);
#pragma unroll
    for (int m = 0; m < 4; m++) {
        int o4 = lane + 32 * m;                  // float4 index: 128 per row
        float4 u = *reinterpret_cast<const float4*>(rowp + o4 * 4);
        float2 va = __half22float2(vp[o4 * 2]);
        float2 vb = __half22float2(vp[o4 * 2 + 1]);
        float4 r;
        r.x = rinv * u.x + va.x;
        r.y = rinv * u.y + va.y;
        r.z = rinv * u.z + vb.x;
        r.w = rinv * u.w + vb.y;
        *reinterpret_cast<float4*>(out + (size_t)row * OUTD_ + o4 * 4) = r;
    }
}

// ---------------------------------------------------------------------------
extern "C" void kernel_launch(void* const* d_in, const int* in_sizes, int n_in,
                              void* d_out, int out_size)
{
    const float* x  = (const float*)d_in[0];
    const float* Wk = (const float*)d_in[1];
    const float* bk = (const float*)d_in[2];
    const float* Wq = (const float*)d_in[3];
    const float* bq = (const float*)d_in[4];
    const float* Wv = (const float*)d_in[5];
    const float* bv = (const float*)d_in[6];
    float* out = (float*)d_out;
    (void)in_sizes; (void)n_in; (void)out_size;

    __half *px, *pw, *pkqv, *pb2, *pk2;
    float *pb, *ppart, *pbig;
    cudaGetSymbolAddress((void**)&px,    h_x);
    cudaGetSymbolAddress((void**)&pw,    h_w);
    cudaGetSymbolAddress((void**)&pb,    g_bias);
    cudaGetSymbolAddress((void**)&pkqv,  h_kqv);
    cudaGetSymbolAddress((void**)&ppart, g_part);
    cudaGetSymbolAddress((void**)&pb2,   h_b2);
    cudaGetSymbolAddress((void**)&pk2,   h_k2);
    cudaGetSymbolAddress((void**)&pbig,  g_big);

    const int smemB = 5 * (128 * 40 + 128 * 40) * 2;   // 102400 B
    cudaFuncSetAttribute(mma_gemm<0>, cudaFuncAttributeMaxDynamicSharedMemorySize, smemB);
    cudaFuncSetAttribute(mma_gemm<3>, cudaFuncAttributeMaxDynamicSharedMemorySize, smemB);
    const int smemT = 4 * (32 * 136) * 2 * 2;          // 69632 B
    cudaFuncSetAttribute(mt_tn, cudaFuncAttributeMaxDynamicSharedMemorySize, smemT);

    // prep (x->fp16, W pack, bias pack) in one launch
    const int NPREP = G_ * IND_ / 2 + NP_ * IND_ / 2 + NP_;
    prep<<<(NPREP + 255) / 256, 256>>>(x, Wk, Wq, Wv, bk, bq, bv, px, pw, pb);

    // fused QKV projection (also emits k2 = [k|k])
    mma_gemm<0><<<dim3(NP_ / 128, G_ / 128), 128, smemB>>>(
        px, pw, pb, pkqv, nullptr, pk2, IND_, IND_, IND_, NP_);

    // Mt = q^T @ [q|v] : TN split-K directly on kqv
    mt_tn<<<dim3(MTN_ / 128, 1, SPLITS_), 128, smemT>>>(pkqv, ppart);
    mt_reduce<<<(KQD_ * MTN_ + 255) / 256, 256>>>(ppart, pb2);

    // big = k2 @ B2^T  ->  [U | y] fp32 [8192 x 640]
    mma_gemm<3><<<dim3(MTN_ / 128, G_ / 128), 128, smemB>>>(
        pk2, pb2, nullptr, nullptr, pbig, nullptr, 256, 256, 256, MTN_);

    // rowwise: sumsq = y.k ; rinv ; out = rinv*U + v
    epilogue<<<G_ / 8, 256>>>(pbig, pkqv, out);
}

// round 13
// speedup vs baseline: 4.0673x; 1.0238x over previous
#include <cuda_runtime.h>
#include <cuda_fp16.h>
#include <cstdint>
#include <cstddef>
#include <math.h>

#define G_    8192
#define IND_  512
#define KQD_  128
#define OUTD_ 512
#define NP_   768     // packed k|q|v columns
#define MTN_  640     // Mt columns = q(128) | v(512)
#define SPLITS_ 16

// ---------------- scratch (static __device__ = allowed) --------------------
__device__ __half h_x[(size_t)G_ * IND_];
__device__ __half h_w[(size_t)NP_ * IND_];        // packed [Wk;Wq;Wv] fp16
__device__ float  g_bias[NP_];                    // packed [bk;bq;bv]
__device__ __half h_kqv[(size_t)G_ * NP_];        // packed [k|q|v] fp16
__device__ float  g_part[(size_t)SPLITS_ * KQD_ * MTN_];  // split-K partials
__device__ __half h_b2[(size_t)MTN_ * 256];       // rows 0-511: W^T hi|lo ; 512-639: Gq hi|lo
__device__ __half h_k2[(size_t)G_ * 256];         // [g][k | k] (written by proj)
__device__ float  g_rinv[G_];

// ---------------- helpers ---------------------------------------------------
__device__ __forceinline__ uint32_t smem_u32(const void* p) {
    uint32_t a;
    asm("{ .reg .u64 t; cvta.to.shared.u64 t, %1; cvt.u32.u64 %0, t; }"
        : "=r"(a) : "l"(p));
    return a;
}
#define CP_ASYNC16(sm, gm) \
    asm volatile("cp.async.cg.shared.global [%0], [%1], 16;" :: "r"(sm), "l"(gm))
#define CP_COMMIT() asm volatile("cp.async.commit_group;" ::: "memory")
#define CP_WAIT(n)  asm volatile("cp.async.wait_group %0;" :: "n"(n) : "memory")

#define LDMX4(r0, r1, r2, r3, addr) \
    asm volatile("ldmatrix.sync.aligned.m8n8.x4.shared.b16 {%0,%1,%2,%3}, [%4];" \
                 : "=r"(r0), "=r"(r1), "=r"(r2), "=r"(r3) : "r"(addr))

#define LDMX4T(r0, r1, r2, r3, addr) \
    asm volatile("ldmatrix.sync.aligned.m8n8.x4.trans.shared.b16 {%0,%1,%2,%3}, [%4];" \
                 : "=r"(r0), "=r"(r1), "=r"(r2), "=r"(r3) : "r"(addr))

__device__ __forceinline__ void mma_f16(float* c, const uint32_t* a, const uint32_t* b) {
    asm volatile(
        "mma.sync.aligned.m16n8k16.row.col.f32.f16.f16.f32 "
        "{%0,%1,%2,%3}, {%4,%5,%6,%7}, {%8,%9}, {%0,%1,%2,%3};"
        : "+f"(c[0]), "+f"(c[1]), "+f"(c[2]), "+f"(c[3])
        : "r"(a[0]), "r"(a[1]), "r"(a[2]), "r"(a[3]), "r"(b[0]), "r"(b[1]));
}

// ===========================================================================
// FP16 GEMM-NT:  C[M,N] = A[M,K] @ B[N,K]^T  (half, row-major)
// Block 128x128, BK=32 halves, 4 warps, warp tile 64x64, 5-stage cp.async.
// MODE 0: Ch = h(acc + bias[col]); colBase==0 tile also writes k2=[k|k]
// MODE 4: no C store; ss[row] = sum_col acc*k[col] -> rinv_out[row]
// MODE 2: Cf[row*ldc+col] = rinv_in[row]*acc + float(kqv[row*NP_+512+col])
// ===========================================================================
template<int MODE>
__global__ void __launch_bounds__(128, 2)
mma_gemm(const __half* __restrict__ A, const __half* __restrict__ B,
         const float* __restrict__ bias, const float* __restrict__ rinv_in,
         const __half* __restrict__ kqv,
         __half* __restrict__ Ch, float* __restrict__ Cf,
         __half* __restrict__ k2out, float* __restrict__ rinv_out,
         int K, int lda, int ldb, int ldc)
{
    constexpr int STAGES = 5;
    constexpr int AS = 128 * 40;
    constexpr int BS = 128 * 40;

    extern __shared__ __half sm[];
    __shared__ float red[128][2];
    const uint32_t sAu = smem_u32(sm);
    const uint32_t sBu = smem_u32(sm + STAGES * AS);

    const int tid  = threadIdx.x;
    const int warp = tid >> 5;
    const int lane = tid & 31;
    const int gr   = lane >> 2;
    const int tc   = lane & 3;
    const int wm   = (warp & 1) * 64;
    const int wn   = (warp >> 1) * 64;
    const int rowBase = blockIdx.y * 128;
    const int colBase = blockIdx.x * 128;

    const int aRow  = wm + (lane & 15);
    const int aColH = (lane >> 4) << 3;
    const int bRow  = wn + ((lane >> 4) << 3) + (lane & 7);
    const int bColH = ((lane >> 3) & 1) << 3;

    float acc[4][8][4];
#pragma unroll
    for (int mi = 0; mi < 4; mi++)
#pragma unroll
        for (int ni = 0; ni < 8; ni++)
#pragma unroll
            for (int r = 0; r < 4; r++) acc[mi][ni][r] = 0.f;

    const int T = K / 32;

    auto load_stage = [&](int it, int buf) {
        const int k0 = it * 32;
#pragma unroll
        for (int l = 0; l < 4; l++) {
            int c = tid + l * 128;
            int r = c >> 2, ck = (c & 3) * 8;
            CP_ASYNC16(sAu + (uint32_t)(buf * AS + r * 40 + ck) * 2,
                       A + (size_t)(rowBase + r) * lda + k0 + ck);
        }
#pragma unroll
        for (int l = 0; l < 4; l++) {
            int c = tid + l * 128;
            int r = c >> 2, ck = (c & 3) * 8;
            CP_ASYNC16(sBu + (uint32_t)(buf * BS + r * 40 + ck) * 2,
                       B + (size_t)(colBase + r) * ldb + k0 + ck);
        }
        CP_COMMIT();
    };

#pragma unroll
    for (int s = 0; s < STAGES - 1; s++)
        if (s < T) load_stage(s, s);

    int buf = 0;
    for (int i = 0; i < T; i++) {
        const int rem = T - 1 - i;
        if (rem >= 3)      { CP_WAIT(3); }
        else if (rem == 2) { CP_WAIT(2); }
        else if (rem == 1) { CP_WAIT(1); }
        else               { CP_WAIT(0); }
        __syncthreads();
        if (i + STAGES - 1 < T) {
            int nb = buf + STAGES - 1; if (nb >= STAGES) nb -= STAGES;
            load_stage(i + STAGES - 1, nb);
        }

        const uint32_t cA = sAu + (uint32_t)(buf * AS) * 2;
        const uint32_t cB = sBu + (uint32_t)(buf * BS) * 2;
#pragma unroll
        for (int ks = 0; ks < 2; ks++) {
            const int kk = ks * 16;
            uint32_t a[4][4], b[8][2];
#pragma unroll
            for (int mi = 0; mi < 4; mi++) {
                uint32_t ad = cA + (uint32_t)((aRow + mi * 16) * 40 + kk + aColH) * 2;
                LDMX4(a[mi][0], a[mi][1], a[mi][2], a[mi][3], ad);
            }
#pragma unroll
            for (int p = 0; p < 4; p++) {
                uint32_t bd = cB + (uint32_t)((bRow + p * 16) * 40 + kk + bColH) * 2;
                LDMX4(b[2 * p][0], b[2 * p][1], b[2 * p + 1][0], b[2 * p + 1][1], bd);
            }
#pragma unroll
            for (int mi = 0; mi < 4; mi++)
#pragma unroll
                for (int ni = 0; ni < 8; ni++)
                    mma_f16(acc[mi][ni], a[mi], b[ni]);
        }
        buf++; if (buf >= STAGES) buf -= STAGES;
    }

    // ---------------- epilogues ----------------
#pragma unroll
    for (int mi = 0; mi < 4; mi++) {
#pragma unroll
        for (int h = 0; h < 2; h++) {
            const int lrow = wm + mi * 16 + h * 8 + gr;
            const int row  = rowBase + lrow;
            float part = 0.f;
            float rv = 0.f;
            if (MODE == 2) rv = rinv_in[row];
#pragma unroll
            for (int ni = 0; ni < 8; ni++) {
                const int col = colBase + wn + ni * 8 + tc * 2;
                float v0 = acc[mi][ni][h * 2 + 0];
                float v1 = acc[mi][ni][h * 2 + 1];
                if (MODE == 0) {
                    __half2 o = __floats2half2_rn(v0 + bias[col], v1 + bias[col + 1]);
                    *reinterpret_cast<__half2*>(Ch + (size_t)row * ldc + col) = o;
                    if (colBase == 0) {
                        *reinterpret_cast<__half2*>(k2out + (size_t)row * 256 + col) = o;
                        *reinterpret_cast<__half2*>(k2out + (size_t)row * 256 + 128 + col) = o;
                    }
                } else if (MODE == 4) {
                    float2 kk2 = __half22float2(
                        *reinterpret_cast<const __half2*>(kqv + (size_t)row * NP_ + col));
                    part += v0 * kk2.x + v1 * kk2.y;
                } else {
                    float2 vv = __half22float2(
                        *reinterpret_cast<const __half2*>(kqv + (size_t)row * NP_ + 2 * KQD_ + col));
                    float2 o;
                    o.x = rv * v0 + vv.x;
                    o.y = rv * v1 + vv.y;
                    *reinterpret_cast<float2*>(Cf + (size_t)row * ldc + col) = o;
                }
            }
            if (MODE == 4) {
                part += __shfl_xor_sync(0xffffffffu, part, 1);
                part += __shfl_xor_sync(0xffffffffu, part, 2);
                if (tc == 0) red[lrow][wn >> 6] = part;
            }
        }
    }
    if (MODE == 4) {
        __syncthreads();
        if (tid < 128) {
            float s = red[tid][0] + red[tid][1];
            rinv_out[rowBase + tid] = 1.0f / fmaxf(sqrtf(s), 1e-12f);
        }
    }
}

// ===========================================================================
// TN split-K GEMM: part[z][d][j] = sum_{g in slice z} kqv[g][128+d]*kqv[g][128+j]
// ===========================================================================
__global__ void __launch_bounds__(128, 2)
mt_tn(const __half* __restrict__ kqv, float* __restrict__ part)
{
    constexpr int STAGES = 4;
    constexpr int TS = 32 * 136;

    extern __shared__ __half sm[];
    const uint32_t sAu = smem_u32(sm);
    const uint32_t sBu = smem_u32(sm + STAGES * TS);

    const int tid  = threadIdx.x;
    const int warp = tid >> 5;
    const int lane = tid & 31;
    const int gr   = lane >> 2;
    const int tc   = lane & 3;
    const int wm   = (warp & 1) * 64;
    const int wn   = (warp >> 1) * 64;
    const int n0   = blockIdx.x * 128;
    const int zb   = blockIdx.z * (G_ / SPLITS_);

    const int aKr = ((lane >> 4) << 3) + (lane & 7);
    const int aMc = ((lane >> 3) & 1) << 3;
    const int bKr = (((lane >> 3) & 1) << 3) + (lane & 7);
    const int bNc = (lane >> 4) << 3;

    float acc[4][8][4];
#pragma unroll
    for (int mi = 0; mi < 4; mi++)
#pragma unroll
        for (int ni = 0; ni < 8; ni++)
#pragma unroll
            for (int r = 0; r < 4; r++) acc[mi][ni][r] = 0.f;

    const int T = (G_ / SPLITS_) / 32;

    auto load_stage = [&](int it, int buf) {
        const int g0 = zb + it * 32;
#pragma unroll
        for (int l = 0; l < 4; l++) {
            int c = tid + l * 128;
            int gro = c >> 4, gc = (c & 15) * 8;
            CP_ASYNC16(sAu + (uint32_t)(buf * TS + gro * 136 + gc) * 2,
                       kqv + (size_t)(g0 + gro) * NP_ + KQD_ + gc);
        }
#pragma unroll
        for (int l = 0; l < 4; l++) {
            int c = tid + l * 128;
            int gro = c >> 4, gc = (c & 15) * 8;
            CP_ASYNC16(sBu + (uint32_t)(buf * TS + gro * 136 + gc) * 2,
                       kqv + (size_t)(g0 + gro) * NP_ + KQD_ + n0 + gc);
        }
        CP_COMMIT();
    };

#pragma unroll
    for (int s = 0; s < STAGES - 1; s++)
        load_stage(s, s);

    int buf = 0;
    for (int i = 0; i < T; i++) {
        const int rem = T - 1 - i;
        if (rem >= 2)      { CP_WAIT(2); }
        else if (rem == 1) { CP_WAIT(1); }
        else               { CP_WAIT(0); }
        __syncthreads();
        if (i + STAGES - 1 < T) {
            int nb = buf + STAGES - 1; if (nb >= STAGES) nb -= STAGES;
            load_stage(i + STAGES - 1, nb);
        }

        const uint32_t cA = sAu + (uint32_t)(buf * TS) * 2;
        const uint32_t cB = sBu + (uint32_t)(buf * TS) * 2;
#pragma unroll
        for (int ks = 0; ks < 2; ks++) {
            const int kk = ks * 16;
            uint32_t a[4][4], b[8][2];
#pragma unroll
            for (int mi = 0; mi < 4; mi++) {
                uint32_t ad = cA + (uint32_t)((kk + aKr) * 136 + wm + mi * 16 + aMc) * 2;
                LDMX4T(a[mi][0], a[mi][1], a[mi][2], a[mi][3], ad);
            }
#pragma unroll
            for (int p = 0; p < 4; p++) {
                uint32_t bd = cB + (uint32_t)((kk + bKr) * 136 + wn + p * 16 + bNc) * 2;
                LDMX4T(b[2 * p][0], b[2 * p][1], b[2 * p + 1][0], b[2 * p + 1][1], bd);
            }
#pragma unroll
            for (int mi = 0; mi < 4; mi++)
#pragma unroll
                for (int ni = 0; ni < 8; ni++)
                    mma_f16(acc[mi][ni], a[mi], b[ni]);
        }
        buf++; if (buf >= STAGES) buf -= STAGES;
    }

    float* dst = part + (size_t)blockIdx.z * KQD_ * MTN_;
#pragma unroll
    for (int mi = 0; mi < 4; mi++)
#pragma unroll
        for (int h = 0; h < 2; h++) {
            const int d = wm + mi * 16 + h * 8 + gr;
#pragma unroll
            for (int ni = 0; ni < 8; ni++) {
                const int col = n0 + wn + ni * 8 + tc * 2;
                float2 o;
                o.x = acc[mi][ni][h * 2 + 0];
                o.y = acc[mi][ni][h * 2 + 1];
                *reinterpret_cast<float2*>(dst + (size_t)d * MTN_ + col) = o;
            }
        }
}

// ---------------------------------------------------------------------------
__global__ void prep(const float* __restrict__ x,
                     const float* __restrict__ wk, const float* __restrict__ wq,
                     const float* __restrict__ wv,
                     const float* __restrict__ bk, const float* __restrict__ bq,
                     const float* __restrict__ bv,
                     __half* __restrict__ hx, __half* __restrict__ hw,
                     float* __restrict__ gb)
{
    const int NX = G_ * IND_ / 2;
    const int NW = NP_ * IND_ / 2;
    int i = blockIdx.x * 256 + threadIdx.x;
    if (i < NX) {
        float2 v = reinterpret_cast<const float2*>(x)[i];
        reinterpret_cast<__half2*>(hx)[i] = __floats2half2_rn(v.x, v.y);
    } else if (i < NX + NW) {
        int j = i - NX;
        int row = j / (IND_ / 2), c2 = j % (IND_ / 2);
        const float* src; int sr;
        if (row < KQD_)          { src = wk; sr = row; }
        else if (row < 2 * KQD_) { src = wq; sr = row - KQD_; }
        else                     { src = wv; sr = row - 2 * KQD_; }
        float2 v = reinterpret_cast<const float2*>(src + (size_t)sr * IND_)[c2];
        reinterpret_cast<__half2*>(hw + (size_t)row * IND_)[c2] = __floats2half2_rn(v.x, v.y);
    } else if (i < NX + NW + NP_) {
        int j = i - NX - NW;
        gb[j] = (j < KQD_) ? bk[j] : (j < 2 * KQD_) ? bq[j - KQD_] : bv[j - 2 * KQD_];
    }
}

// vectorized reduce: 4 consecutive j per thread (never straddles j=128)
__global__ void mt_reduce(const float* __restrict__ part, __half* __restrict__ b2)
{
    int i4 = blockIdx.x * 256 + threadIdx.x;       // over 128*640/4 = 20480
    if (i4 >= KQD_ * MTN_ / 4) return;
    int d  = i4 / (MTN_ / 4);
    int j0 = (i4 % (MTN_ / 4)) * 4;
    float4 s = make_float4(0.f, 0.f, 0.f, 0.f);
#pragma unroll
    for (int z = 0; z < SPLITS_; z++) {
        float4 p = *reinterpret_cast<const float4*>(
            part + (size_t)z * KQD_ * MTN_ + (size_t)d * MTN_ + j0);
        s.x += p.x; s.y += p.y; s.z += p.z; s.w += p.w;
    }
    float sv[4] = {s.x, s.y, s.z, s.w};
#pragma unroll
    for (int e = 0; e < 4; e++) {
        int j = j0 + e;
        int r = (j < KQD_) ? (512 + j) : (j - KQD_);
        __half hi = __float2half_rn(sv[e]);
        b2[(size_t)r * 256 + d]       = hi;
        b2[(size_t)r * 256 + 128 + d] = __float2half_rn(sv[e] - __half2float(hi));
    }
}

// ---------------------------------------------------------------------------
extern "C" void kernel_launch(void* const* d_in, const int* in_sizes, int n_in,
                              void* d_out, int out_size)
{
    const float* x  = (const float*)d_in[0];
    const float* Wk = (const float*)d_in[1];
    const float* bk = (const float*)d_in[2];
    const float* Wq = (const float*)d_in[3];
    const float* bq = (const float*)d_in[4];
    const float* Wv = (const float*)d_in[5];
    const float* bv = (const float*)d_in[6];
    float* out = (float*)d_out;
    (void)in_sizes; (void)n_in; (void)out_size;

    __half *px, *pw, *pkqv, *pb2, *pk2;
    float *pb, *ppart, *pr;
    cudaGetSymbolAddress((void**)&px,    h_x);
    cudaGetSymbolAddress((void**)&pw,    h_w);
    cudaGetSymbolAddress((void**)&pb,    g_bias);
    cudaGetSymbolAddress((void**)&pkqv,  h_kqv);
    cudaGetSymbolAddress((void**)&ppart, g_part);
    cudaGetSymbolAddress((void**)&pb2,   h_b2);
    cudaGetSymbolAddress((void**)&pk2,   h_k2);
    cudaGetSymbolAddress((void**)&pr,    g_rinv);

    const int smemB = 5 * (128 * 40 + 128 * 40) * 2;   // 102400 B
    cudaFuncSetAttribute(mma_gemm<0>, cudaFuncAttributeMaxDynamicSharedMemorySize, smemB);
    cudaFuncSetAttribute(mma_gemm<4>, cudaFuncAttributeMaxDynamicSharedMemorySize, smemB);
    cudaFuncSetAttribute(mma_gemm<2>, cudaFuncAttributeMaxDynamicSharedMemorySize, smemB);
    const int smemT = 4 * (32 * 136) * 2 * 2;          // 69632 B
    cudaFuncSetAttribute(mt_tn, cudaFuncAttributeMaxDynamicSharedMemorySize, smemT);

    // prep (x->fp16, W pack, bias pack)
    const int NPREP = G_ * IND_ / 2 + NP_ * IND_ / 2 + NP_;
    prep<<<(NPREP + 255) / 256, 256>>>(x, Wk, Wq, Wv, bk, bq, bv, px, pw, pb);

    // fused QKV projection (emits kqv and k2=[k|k])
    mma_gemm<0><<<dim3(NP_ / 128, G_ / 128), 128, smemB>>>(
        px, pw, pb, nullptr, nullptr, pkqv, nullptr, pk2, nullptr,
        IND_, IND_, IND_, NP_);

    // Mt = q^T @ [q|v] (TN split-K) -> reduce into B2 hi|lo
    mt_tn<<<dim3(MTN_ / 128, 1, SPLITS_), 128, smemT>>>(pkqv, ppart);
    mt_reduce<<<(KQD_ * MTN_ / 4 + 255) / 256, 256>>>(ppart, pb2);

    // rinv: y = k @ Gq (N=128), ss = y.k computed in-register -> rinv
    mma_gemm<4><<<dim3(1, G_ / 128), 128, smemB>>>(
        pk2, pb2 + (size_t)512 * 256, nullptr, nullptr, pkqv,
        nullptr, nullptr, nullptr, pr, 256, 256, 256, KQD_);

    // out = rinv[row] * (k @ W) + v   (N=512, writes out directly)
    mma_gemm<2><<<dim3(OUTD_ / 128, G_ / 128), 128, smemB>>>(
        pk2, pb2, nullptr, pr, pkqv, nullptr, out, nullptr, nullptr,
        256, 256, 256, OUTD_);
}

// round 14
// speedup vs baseline: 4.2707x; 1.0500x over previous
#include <cuda_runtime.h>
#include <cuda_fp16.h>
#include <cstdint>
#include <cstddef>
#include <math.h>

#define G_    8192
#define IND_  512
#define KQD_  128
#define OUTD_ 512
#define NP_   768     // packed k|q|v columns
#define MTN_  640     // Mt columns = q(128) | v(512)
#define SPLITS_ 16

// ---------------- scratch (static __device__ = allowed) --------------------
__device__ __half h_x[(size_t)G_ * IND_];
__device__ __half h_w[(size_t)NP_ * IND_];        // packed [Wk;Wq;Wv] fp16
__device__ float  g_bias[NP_];                    // packed [bk;bq;bv]
__device__ __half h_kqv[(size_t)G_ * NP_];        // packed [k|q|v] fp16
__device__ float  g_part[(size_t)SPLITS_ * KQD_ * MTN_];  // split-K partials
__device__ __half h_b2[(size_t)MTN_ * 256];       // rows 0-511: W^T hi|lo ; 512-639: Gq hi|lo
__device__ __half h_k2[(size_t)G_ * 256];         // [g][k | k] (written by proj)
__device__ float  g_rinv[G_];

// ---------------- helpers ---------------------------------------------------
__device__ __forceinline__ uint32_t smem_u32(const void* p) {
    uint32_t a;
    asm("{ .reg .u64 t; cvta.to.shared.u64 t, %1; cvt.u32.u64 %0, t; }"
        : "=r"(a) : "l"(p));
    return a;
}
#define CP_ASYNC16(sm, gm) \
    asm volatile("cp.async.cg.shared.global [%0], [%1], 16;" :: "r"(sm), "l"(gm))
#define CP_COMMIT() asm volatile("cp.async.commit_group;" ::: "memory")
#define CP_WAIT(n)  asm volatile("cp.async.wait_group %0;" :: "n"(n) : "memory")

#define LDMX4(r0, r1, r2, r3, addr) \
    asm volatile("ldmatrix.sync.aligned.m8n8.x4.shared.b16 {%0,%1,%2,%3}, [%4];" \
                 : "=r"(r0), "=r"(r1), "=r"(r2), "=r"(r3) : "r"(addr))

#define LDMX4T(r0, r1, r2, r3, addr) \
    asm volatile("ldmatrix.sync.aligned.m8n8.x4.trans.shared.b16 {%0,%1,%2,%3}, [%4];" \
                 : "=r"(r0), "=r"(r1), "=r"(r2), "=r"(r3) : "r"(addr))

__device__ __forceinline__ void mma_f16(float* c, const uint32_t* a, const uint32_t* b) {
    asm volatile(
        "mma.sync.aligned.m16n8k16.row.col.f32.f16.f16.f32 "
        "{%0,%1,%2,%3}, {%4,%5,%6,%7}, {%8,%9}, {%0,%1,%2,%3};"
        : "+f"(c[0]), "+f"(c[1]), "+f"(c[2]), "+f"(c[3])
        : "r"(a[0]), "r"(a[1]), "r"(a[2]), "r"(a[3]), "r"(b[0]), "r"(b[1]));
}

// ===========================================================================
// FP16 GEMM-NT:  C[M,N] = A[M,K] @ B[N,K]^T  (half, row-major)
// Block 128x128, BK=32 halves, 4 warps, warp tile 64x64, 5-stage cp.async.
// MODE 0: Ch = h(acc + bias[col]); colBase==0 tile also writes k2=[k|k]
// MODE 4: no C store; ss[row] = sum_col acc*k[col] -> rinv_out[row]
// MODE 2: Cf[row*ldc+col] = rinv_in[row]*acc + float(kqv[row*NP_+512+col])
// ===========================================================================
template<int MODE>
__global__ void __launch_bounds__(128, 2)
mma_gemm(const __half* __restrict__ A, const __half* __restrict__ B,
         const float* __restrict__ bias, const float* __restrict__ rinv_in,
         const __half* __restrict__ kqv,
         __half* __restrict__ Ch, float* __restrict__ Cf,
         __half* __restrict__ k2out, float* __restrict__ rinv_out,
         int K, int lda, int ldb, int ldc)
{
    constexpr int STAGES = 5;
    constexpr int AS = 128 * 40;
    constexpr int BS = 128 * 40;

    extern __shared__ __half sm[];
    __shared__ float red[128][2];
    const uint32_t sAu = smem_u32(sm);
    const uint32_t sBu = smem_u32(sm + STAGES * AS);

    const int tid  = threadIdx.x;
    const int warp = tid >> 5;
    const int lane = tid & 31;
    const int gr   = lane >> 2;
    const int tc   = lane & 3;
    const int wm   = (warp & 1) * 64;
    const int wn   = (warp >> 1) * 64;
    const int rowBase = blockIdx.y * 128;
    const int colBase = blockIdx.x * 128;

    const int aRow  = wm + (lane & 15);
    const int aColH = (lane >> 4) << 3;
    const int bRow  = wn + ((lane >> 4) << 3) + (lane & 7);
    const int bColH = ((lane >> 3) & 1) << 3;

    float acc[4][8][4];
#pragma unroll
    for (int mi = 0; mi < 4; mi++)
#pragma unroll
        for (int ni = 0; ni < 8; ni++)
#pragma unroll
            for (int r = 0; r < 4; r++) acc[mi][ni][r] = 0.f;

    const int T = K / 32;

    auto load_stage = [&](int it, int buf) {
        const int k0 = it * 32;
#pragma unroll
        for (int l = 0; l < 4; l++) {
            int c = tid + l * 128;
            int r = c >> 2, ck = (c & 3) * 8;
            CP_ASYNC16(sAu + (uint32_t)(buf * AS + r * 40 + ck) * 2,
                       A + (size_t)(rowBase + r) * lda + k0 + ck);
        }
#pragma unroll
        for (int l = 0; l < 4; l++) {
            int c = tid + l * 128;
            int r = c >> 2, ck = (c & 3) * 8;
            CP_ASYNC16(sBu + (uint32_t)(buf * BS + r * 40 + ck) * 2,
                       B + (size_t)(colBase + r) * ldb + k0 + ck);
        }
        CP_COMMIT();
    };

#pragma unroll
    for (int s = 0; s < STAGES - 1; s++)
        if (s < T) load_stage(s, s);

    int buf = 0;
    for (int i = 0; i < T; i++) {
        const int rem = T - 1 - i;
        if (rem >= 3)      { CP_WAIT(3); }
        else if (rem == 2) { CP_WAIT(2); }
        else if (rem == 1) { CP_WAIT(1); }
        else               { CP_WAIT(0); }
        __syncthreads();
        if (i + STAGES - 1 < T) {
            int nb = buf + STAGES - 1; if (nb >= STAGES) nb -= STAGES;
            load_stage(i + STAGES - 1, nb);
        }

        const uint32_t cA = sAu + (uint32_t)(buf * AS) * 2;
        const uint32_t cB = sBu + (uint32_t)(buf * BS) * 2;
#pragma unroll
        for (int ks = 0; ks < 2; ks++) {
            const int kk = ks * 16;
            uint32_t a[4][4], b[8][2];
#pragma unroll
            for (int mi = 0; mi < 4; mi++) {
                uint32_t ad = cA + (uint32_t)((aRow + mi * 16) * 40 + kk + aColH) * 2;
                LDMX4(a[mi][0], a[mi][1], a[mi][2], a[mi][3], ad);
            }
#pragma unroll
            for (int p = 0; p < 4; p++) {
                uint32_t bd = cB + (uint32_t)((bRow + p * 16) * 40 + kk + bColH) * 2;
                LDMX4(b[2 * p][0], b[2 * p][1], b[2 * p + 1][0], b[2 * p + 1][1], bd);
            }
#pragma unroll
            for (int mi = 0; mi < 4; mi++)
#pragma unroll
                for (int ni = 0; ni < 8; ni++)
                    mma_f16(acc[mi][ni], a[mi], b[ni]);
        }
        buf++; if (buf >= STAGES) buf -= STAGES;
    }

    // ---------------- epilogues ----------------
#pragma unroll
    for (int mi = 0; mi < 4; mi++) {
#pragma unroll
        for (int h = 0; h < 2; h++) {
            const int lrow = wm + mi * 16 + h * 8 + gr;
            const int row  = rowBase + lrow;
            float part = 0.f;
            float rv = 0.f;
            if (MODE == 2) rv = rinv_in[row];
#pragma unroll
            for (int ni = 0; ni < 8; ni++) {
                const int col = colBase + wn + ni * 8 + tc * 2;
                float v0 = acc[mi][ni][h * 2 + 0];
                float v1 = acc[mi][ni][h * 2 + 1];
                if (MODE == 0) {
                    __half2 o = __floats2half2_rn(v0 + bias[col], v1 + bias[col + 1]);
                    *reinterpret_cast<__half2*>(Ch + (size_t)row * ldc + col) = o;
                    if (colBase == 0) {
                        *reinterpret_cast<__half2*>(k2out + (size_t)row * 256 + col) = o;
                        *reinterpret_cast<__half2*>(k2out + (size_t)row * 256 + 128 + col) = o;
                    }
                } else if (MODE == 4) {
                    float2 kk2 = __half22float2(
                        *reinterpret_cast<const __half2*>(kqv + (size_t)row * NP_ + col));
                    part += v0 * kk2.x + v1 * kk2.y;
                } else {
                    float2 vv = __half22float2(
                        *reinterpret_cast<const __half2*>(kqv + (size_t)row * NP_ + 2 * KQD_ + col));
                    float2 o;
                    o.x = rv * v0 + vv.x;
                    o.y = rv * v1 + vv.y;
                    *reinterpret_cast<float2*>(Cf + (size_t)row * ldc + col) = o;
                }
            }
            if (MODE == 4) {
                part += __shfl_xor_sync(0xffffffffu, part, 1);
                part += __shfl_xor_sync(0xffffffffu, part, 2);
                if (tc == 0) red[lrow][wn >> 6] = part;
            }
        }
    }
    if (MODE == 4) {
        __syncthreads();
        if (tid < 128) {
            float s = red[tid][0] + red[tid][1];
            rinv_out[rowBase + tid] = 1.0f / fmaxf(sqrtf(s), 1e-12f);
        }
    }
}

// ===========================================================================
// TN split-K GEMM: part[z][d][j] = sum_{g in slice z} kqv[g][128+d]*kqv[g][128+j]
// M=128 (d), N tile = 64 -> grid (10, 1, 16) = 160 CTAs.
// A smem: 32 g x 136 halves ; B smem: 32 g x 72 halves. ldmatrix.trans frags.
// ===========================================================================
__global__ void __launch_bounds__(128, 2)
mt_tn(const __half* __restrict__ kqv, float* __restrict__ part)
{
    constexpr int STAGES = 4;
    constexpr int TSA = 32 * 136;
    constexpr int TSB = 32 * 72;

    extern __shared__ __half sm[];
    const uint32_t sAu = smem_u32(sm);
    const uint32_t sBu = smem_u32(sm + STAGES * TSA);

    const int tid  = threadIdx.x;
    const int warp = tid >> 5;
    const int lane = tid & 31;
    const int gr   = lane >> 2;
    const int tc   = lane & 3;
    const int wm   = (warp & 1) * 64;    // 2 warps in m (128)
    const int wn   = (warp >> 1) * 32;   // 2 warps in n (64)
    const int n0   = blockIdx.x * 64;
    const int zb   = blockIdx.z * (G_ / SPLITS_);

    const int aKr = ((lane >> 4) << 3) + (lane & 7);
    const int aMc = ((lane >> 3) & 1) << 3;
    const int bKr = (((lane >> 3) & 1) << 3) + (lane & 7);
    const int bNc = (lane >> 4) << 3;

    float acc[4][4][4];
#pragma unroll
    for (int mi = 0; mi < 4; mi++)
#pragma unroll
        for (int ni = 0; ni < 4; ni++)
#pragma unroll
            for (int r = 0; r < 4; r++) acc[mi][ni][r] = 0.f;

    const int T = (G_ / SPLITS_) / 32;

    auto load_stage = [&](int it, int buf) {
        const int g0 = zb + it * 32;
#pragma unroll
        for (int l = 0; l < 4; l++) {
            int c = tid + l * 128;
            int gro = c >> 4, gc = (c & 15) * 8;
            CP_ASYNC16(sAu + (uint32_t)(buf * TSA + gro * 136 + gc) * 2,
                       kqv + (size_t)(g0 + gro) * NP_ + KQD_ + gc);
        }
#pragma unroll
        for (int l = 0; l < 2; l++) {
            int c = tid + l * 128;
            int gro = c >> 3, gc = (c & 7) * 8;
            CP_ASYNC16(sBu + (uint32_t)(buf * TSB + gro * 72 + gc) * 2,
                       kqv + (size_t)(g0 + gro) * NP_ + KQD_ + n0 + gc);
        }
        CP_COMMIT();
    };

#pragma unroll
    for (int s = 0; s < STAGES - 1; s++)
        load_stage(s, s);

    int buf = 0;
    for (int i = 0; i < T; i++) {
        const int rem = T - 1 - i;
        if (rem >= 2)      { CP_WAIT(2); }
        else if (rem == 1) { CP_WAIT(1); }
        else               { CP_WAIT(0); }
        __syncthreads();
        if (i + STAGES - 1 < T) {
            int nb = buf + STAGES - 1; if (nb >= STAGES) nb -= STAGES;
            load_stage(i + STAGES - 1, nb);
        }

        const uint32_t cA = sAu + (uint32_t)(buf * TSA) * 2;
        const uint32_t cB = sBu + (uint32_t)(buf * TSB) * 2;
#pragma unroll
        for (int ks = 0; ks < 2; ks++) {
            const int kk = ks * 16;
            uint32_t a[4][4], b[4][2];
#pragma unroll
            for (int mi = 0; mi < 4; mi++) {
                uint32_t ad = cA + (uint32_t)((kk + aKr) * 136 + wm + mi * 16 + aMc) * 2;
                LDMX4T(a[mi][0], a[mi][1], a[mi][2], a[mi][3], ad);
            }
#pragma unroll
            for (int p = 0; p < 2; p++) {
                uint32_t bd = cB + (uint32_t)((kk + bKr) * 72 + wn + p * 16 + bNc) * 2;
                LDMX4T(b[2 * p][0], b[2 * p][1], b[2 * p + 1][0], b[2 * p + 1][1], bd);
            }
#pragma unroll
            for (int mi = 0; mi < 4; mi++)
#pragma unroll
                for (int ni = 0; ni < 4; ni++)
                    mma_f16(acc[mi][ni], a[mi], b[ni]);
        }
        buf++; if (buf >= STAGES) buf -= STAGES;
    }

    float* dst = part + (size_t)blockIdx.z * KQD_ * MTN_;
#pragma unroll
    for (int mi = 0; mi < 4; mi++)
#pragma unroll
        for (int h = 0; h < 2; h++) {
            const int d = wm + mi * 16 + h * 8 + gr;
#pragma unroll
            for (int ni = 0; ni < 4; ni++) {
                const int col = n0 + wn + ni * 8 + tc * 2;
                float2 o;
                o.x = acc[mi][ni][h * 2 + 0];
                o.y = acc[mi][ni][h * 2 + 1];
                *reinterpret_cast<float2*>(dst + (size_t)d * MTN_ + col) = o;
            }
        }
}

// ---------------------------------------------------------------------------
__global__ void prep(const float* __restrict__ x,
                     const float* __restrict__ wk, const float* __restrict__ wq,
                     const float* __restrict__ wv,
                     const float* __restrict__ bk, const float* __restrict__ bq,
                     const float* __restrict__ bv,
                     __half* __restrict__ hx, __half* __restrict__ hw,
                     float* __restrict__ gb)
{
    const int NX = G_ * IND_ / 2;
    const int NW = NP_ * IND_ / 2;
    int i = blockIdx.x * 256 + threadIdx.x;
    if (i < NX) {
        float2 v = reinterpret_cast<const float2*>(x)[i];
        reinterpret_cast<__half2*>(hx)[i] = __floats2half2_rn(v.x, v.y);
    } else if (i < NX + NW) {
        int j = i - NX;
        int row = j / (IND_ / 2), c2 = j % (IND_ / 2);
        const float* src; int sr;
        if (row < KQD_)          { src = wk; sr = row; }
        else if (row < 2 * KQD_) { src = wq; sr = row - KQD_; }
        else                     { src = wv; sr = row - 2 * KQD_; }
        float2 v = reinterpret_cast<const float2*>(src + (size_t)sr * IND_)[c2];
        reinterpret_cast<__half2*>(hw + (size_t)row * IND_)[c2] = __floats2half2_rn(v.x, v.y);
    } else if (i < NX + NW + NP_) {
        int j = i - NX - NW;
        gb[j] = (j < KQD_) ? bk[j] : (j < 2 * KQD_) ? bq[j - KQD_] : bv[j - 2 * KQD_];
    }
}

// reduce: 4 threads per float4-element, each sums 4 z-slices, shfl combine.
// 81920 threads = 320 CTAs.
__global__ void mt_reduce(const float* __restrict__ part, __half* __restrict__ b2)
{
    const int t    = blockIdx.x * 256 + threadIdx.x;
    const int sub  = t & 3;                       // which z-quarter
    const int e    = t >> 2;                      // float4 element id (0..20479)
    if (e >= KQD_ * MTN_ / 4) return;
    const int d  = e / (MTN_ / 4);
    const int j0 = (e % (MTN_ / 4)) * 4;

    float4 s = make_float4(0.f, 0.f, 0.f, 0.f);
#pragma unroll
    for (int zz = 0; zz < 4; zz++) {
        int z = sub * 4 + zz;
        float4 p = *reinterpret_cast<const float4*>(
            part + (size_t)z * KQD_ * MTN_ + (size_t)d * MTN_ + j0);
        s.x += p.x; s.y += p.y; s.z += p.z; s.w += p.w;
    }
#pragma unroll
    for (int off = 1; off <= 2; off <<= 1) {
        s.x += __shfl_xor_sync(0xffffffffu, s.x, off);
        s.y += __shfl_xor_sync(0xffffffffu, s.y, off);
        s.z += __shfl_xor_sync(0xffffffffu, s.z, off);
        s.w += __shfl_xor_sync(0xffffffffu, s.w, off);
    }
    if (sub == 0) {
        float sv[4] = {s.x, s.y, s.z, s.w};
#pragma unroll
        for (int el = 0; el < 4; el++) {
            int j = j0 + el;
            int r = (j < KQD_) ? (512 + j) : (j - KQD_);
            __half hi = __float2half_rn(sv[el]);
            b2[(size_t)r * 256 + d]       = hi;
            b2[(size_t)r * 256 + 128 + d] = __float2half_rn(sv[el] - __half2float(hi));
        }
    }
}

// ---------------------------------------------------------------------------
extern "C" void kernel_launch(void* const* d_in, const int* in_sizes, int n_in,
                              void* d_out, int out_size)
{
    const float* x  = (const float*)d_in[0];
    const float* Wk = (const float*)d_in[1];
    const float* bk = (const float*)d_in[2];
    const float* Wq = (const float*)d_in[3];
    const float* bq = (const float*)d_in[4];
    const float* Wv = (const float*)d_in[5];
    const float* bv = (const float*)d_in[6];
    float* out = (float*)d_out;
    (void)in_sizes; (void)n_in; (void)out_size;

    __half *px, *pw, *pkqv, *pb2, *pk2;
    float *pb, *ppart, *pr;
    cudaGetSymbolAddress((void**)&px,    h_x);
    cudaGetSymbolAddress((void**)&pw,    h_w);
    cudaGetSymbolAddress((void**)&pb,    g_bias);
    cudaGetSymbolAddress((void**)&pkqv,  h_kqv);
    cudaGetSymbolAddress((void**)&ppart, g_part);
    cudaGetSymbolAddress((void**)&pb2,   h_b2);
    cudaGetSymbolAddress((void**)&pk2,   h_k2);
    cudaGetSymbolAddress((void**)&pr,    g_rinv);

    const int smemB = 5 * (128 * 40 + 128 * 40) * 2;   // 102400 B
    cudaFuncSetAttribute(mma_gemm<0>, cudaFuncAttributeMaxDynamicSharedMemorySize, smemB);
    cudaFuncSetAttribute(mma_gemm<4>, cudaFuncAttributeMaxDynamicSharedMemorySize, smemB);
    cudaFuncSetAttribute(mma_gemm<2>, cudaFuncAttributeMaxDynamicSharedMemorySize, smemB);
    const int smemT = 4 * (32 * 136 + 32 * 72) * 2;    // 53248 B
    cudaFuncSetAttribute(mt_tn, cudaFuncAttributeMaxDynamicSharedMemorySize, smemT);

    // prep (x->fp16, W pack, bias pack)
    const int NPREP = G_ * IND_ / 2 + NP_ * IND_ / 2 + NP_;
    prep<<<(NPREP + 255) / 256, 256>>>(x, Wk, Wq, Wv, bk, bq, bv, px, pw, pb);

    // fused QKV projection (emits kqv and k2=[k|k])
    mma_gemm<0><<<dim3(NP_ / 128, G_ / 128), 128, smemB>>>(
        px, pw, pb, nullptr, nullptr, pkqv, nullptr, pk2, nullptr,
        IND_, IND_, IND_, NP_);

    // Mt = q^T @ [q|v] (TN split-K, N-tile 64 -> 160 CTAs) -> reduce into B2
    mt_tn<<<dim3(MTN_ / 64, 1, SPLITS_), 128, smemT>>>(pkqv, ppart);
    mt_reduce<<<(KQD_ * MTN_ + 255) / 256, 256>>>(ppart, pb2);

    // rinv: y = k @ Gq (N=128), ss = y.k computed in-register -> rinv
    mma_gemm<4><<<dim3(1, G_ / 128), 128, smemB>>>(
        pk2, pb2 + (size_t)512 * 256, nullptr, nullptr, pkqv,
        nullptr, nullptr, nullptr, pr, 256, 256, 256, KQD_);

    // out = rinv[row] * (k @ W) + v   (N=512, writes out directly)
    mma_gemm<2><<<dim3(OUTD_ / 128, G_ / 128), 128, smemB>>>(
        pk2, pb2, nullptr, pr, pkqv, nullptr, out, nullptr, nullptr,
        256, 256, 256, OUTD_);
}